// round 7
// baseline (speedup 1.0000x reference)
#include <cuda_runtime.h>
#include <cuda_bf16.h>
#include <cstdint>

// ---------------------------------------------------------------------------
// DeepFeatureMatcher: bf16 mma.sync screening GEMM (CTA tile 128x256, warp
// tile 64x64, cp.async double buffer) -> per-tile bidirectional top-2 ->
// hierarchical merge to 4 candidates -> exact fp32 rescore -> mutual+ratio.
// Output (float32, 3*12288): [masked_sim | nn12 as float | mask as 0/1]
// ---------------------------------------------------------------------------

#define N_DESC 12288
#define CH     512
#define NTI    96                    // 128-row tiles
#define NTJ    48                    // 256-col tiles
#define RATIO_T 0.95f
#define EPS_T   1e-8f
#define STAGE_SZ 49152               // 16KB A + 32KB B per stage
#define SMEM_GEMM (2 * STAGE_SZ)     // 96 KB double buffer

// ---- device global scratch (no allocation allowed) ------------------------
__device__ __align__(256) float         g_fA[N_DESC * CH];  // normalized fp32, desc-major
__device__ __align__(256) float         g_fB[N_DESC * CH];
__device__ __align__(256) __nv_bfloat16 g_bA[N_DESC * CH];  // normalized bf16, desc-major
__device__ __align__(256) __nv_bfloat16 g_bB[N_DESC * CH];
__device__ float g_rnA[N_DESC], g_rnB[N_DESC];
// per-tile top2 partials: rows over col-tiles [NTJ][N], cols over row-tiles [NTI][N]
__device__ float g_rowV1[NTJ * N_DESC], g_rowV2[NTJ * N_DESC];
__device__ int   g_rowI1[NTJ * N_DESC], g_rowI2[NTJ * N_DESC];
__device__ float g_colV1[NTI * N_DESC], g_colV2[NTI * N_DESC];
__device__ int   g_colI1[NTI * N_DESC], g_colI2[NTI * N_DESC];
// level-1 merged (8 groups), per dir
__device__ float g_l1V1[2 * 8 * N_DESC], g_l1V2[2 * 8 * N_DESC];
__device__ int   g_l1I1[2 * 8 * N_DESC], g_l1I2[2 * 8 * N_DESC];
// 4 candidates per row/col, per dir
__device__ int   g_cI[2 * 4 * N_DESC];
// rescored fp32 top-2
__device__ float g_aV1[N_DESC], g_aV2[N_DESC]; __device__ int g_aI1[N_DESC];
__device__ float g_bV1[N_DESC], g_bV2[N_DESC]; __device__ int g_bI1[N_DESC];

// ---- helpers --------------------------------------------------------------
__device__ __forceinline__ uint32_t smem_u32(const void* p) {
    uint32_t a;
    asm("{ .reg .u64 t; cvta.to.shared.u64 t, %1; cvt.u32.u64 %0, t; }"
        : "=r"(a) : "l"(p));
    return a;
}
__device__ __forceinline__ void ldmx4(uint32_t& r0, uint32_t& r1,
                                      uint32_t& r2, uint32_t& r3, uint32_t addr) {
    asm volatile("ldmatrix.sync.aligned.m8n8.x4.shared.b16 {%0,%1,%2,%3}, [%4];"
                 : "=r"(r0), "=r"(r1), "=r"(r2), "=r"(r3) : "r"(addr));
}
__device__ __forceinline__ void mma16816(float* c, const uint32_t* a,
                                         const uint32_t* b) {
    asm volatile(
        "mma.sync.aligned.m16n8k16.row.col.f32.bf16.bf16.f32 "
        "{%0,%1,%2,%3}, {%4,%5,%6,%7}, {%8,%9}, {%0,%1,%2,%3};"
        : "+f"(c[0]), "+f"(c[1]), "+f"(c[2]), "+f"(c[3])
        : "r"(a[0]), "r"(a[1]), "r"(a[2]), "r"(a[3]), "r"(b[0]), "r"(b[1]));
}
// merge top-2 list (w1,j1,w2,j2) into (v1,i1,v2,i2); lower index wins ties
__device__ __forceinline__ void merge22(float& v1, int& i1, float& v2, int& i2,
                                        float w1, int j1, float w2, int j2) {
    if (w1 > v1 || (w1 == v1 && j1 < i1)) {
        if (v1 > w2 || (v1 == w2 && i1 < j2)) { v2 = v1; i2 = i1; }
        else                                   { v2 = w2; i2 = j2; }
        v1 = w1; i1 = j1;
    } else if (w1 > v2 || (w1 == v2 && j1 < i2)) {
        v2 = w1; i2 = j1;
    }
}

// ---- kernel 1: inverse norms ----------------------------------------------
__global__ void norms_kernel(const float* __restrict__ mA,
                             const float* __restrict__ mB) {
    int i = blockIdx.x * blockDim.x + threadIdx.x;
    if (i >= N_DESC) return;
    const float* m = blockIdx.y ? mB : mA;
    float s = 0.f;
    #pragma unroll 8
    for (int c = 0; c < CH; ++c) {
        float v = m[(size_t)c * N_DESC + i];
        s = fmaf(v, v, s);
    }
    float r = 1.0f / sqrtf(s);
    if (blockIdx.y) g_rnB[i] = r; else g_rnA[i] = r;
}

// ---- kernel 2: normalize + transpose -> fp32 and bf16 desc-major ----------
__global__ void prep_kernel(const float* __restrict__ mA,
                            const float* __restrict__ mB) {
    __shared__ float t[64][65];
    const int tid = threadIdx.x;
    const int i0 = blockIdx.x * 64;
    const int c0 = blockIdx.y * 64;
    const float* m = blockIdx.z ? mB : mA;
    const float* rn = blockIdx.z ? g_rnB : g_rnA;
    float* gf = blockIdx.z ? g_fB : g_fA;
    __nv_bfloat16* gb = blockIdx.z ? g_bB : g_bA;

    const int ii = tid & 63, cb = tid >> 6;
    #pragma unroll
    for (int it = 0; it < 16; ++it) {
        int cc = it * 4 + cb;
        t[cc][ii] = m[(size_t)(c0 + cc) * N_DESC + i0 + ii] * rn[i0 + ii];
    }
    __syncthreads();

    const int cc2 = tid & 31, rw = tid >> 5;
    #pragma unroll
    for (int it = 0; it < 8; ++it) {
        int i = rw + it * 8;
        float v0 = t[2 * cc2][i], v1 = t[2 * cc2 + 1][i];
        size_t base = (size_t)(i0 + i) * CH + c0 + 2 * cc2;
        *reinterpret_cast<float2*>(&gf[base]) = make_float2(v0, v1);
        uint32_t pk = ((uint32_t)__bfloat16_as_ushort(__float2bfloat16_rn(v1)) << 16) |
                      (uint32_t)__bfloat16_as_ushort(__float2bfloat16_rn(v0));
        *reinterpret_cast<uint32_t*>(&gb[base]) = pk;
    }
}

// ---- kernel 3: bf16 screening GEMM (128x256 tile) + per-tile top-2 --------
extern __shared__ char dsmem[];
__global__ __launch_bounds__(256, 1) void gemm_top2_kernel() {
    const int tid = threadIdx.x;
    const int wid = tid >> 5, lane = tid & 31;
    const int wm = wid >> 2, wn = wid & 3;     // warp tile: 64 rows x 64 cols
    const int grp = lane >> 3, lr = lane & 7;
    const int gq = lane >> 2, tq = lane & 3;
    const int iT = blockIdx.x, jT = blockIdx.y;
    const int i0 = iT * 128, j0 = jT * 256;
    const uint32_t sb = smem_u32(dsmem);

    float acc[4][8][4];
    #pragma unroll
    for (int mi = 0; mi < 4; ++mi)
        #pragma unroll
        for (int ni = 0; ni < 8; ++ni)
            #pragma unroll
            for (int c = 0; c < 4; ++c) acc[mi][ni][c] = 0.f;

    const int r0 = tid >> 3;       // staging row 0..31
    const int c8 = tid & 7;        // 16B sector
    const uint32_t swb = ((uint32_t)r0 * 128 + c8 * 16);
    const uint32_t swo = swb ^ ((swb >> 3) & 0x70);   // swizzled offset, +4096/row32

    // ---- cp.async staging: A 128x64, B 256x64 bf16, SW128 ------------------
    #define STAGE(buf, chn) do {                                               \
        const size_t kof = (size_t)(chn) * 64 + c8 * 8;                        \
        _Pragma("unroll")                                                      \
        for (int it = 0; it < 4; ++it) {                                       \
            const __nv_bfloat16* ga = g_bA + (size_t)(i0 + r0 + it * 32) * CH + kof; \
            uint32_t da = sb + (buf) * STAGE_SZ + it * 4096 + swo;             \
            asm volatile("cp.async.cg.shared.global [%0], [%1], 16;"           \
                         :: "r"(da), "l"(ga) : "memory");                      \
        }                                                                      \
        _Pragma("unroll")                                                      \
        for (int it = 0; it < 8; ++it) {                                       \
            const __nv_bfloat16* gbp = g_bB + (size_t)(j0 + r0 + it * 32) * CH + kof; \
            uint32_t db = sb + (buf) * STAGE_SZ + 16384 + it * 4096 + swo;     \
            asm volatile("cp.async.cg.shared.global [%0], [%1], 16;"           \
                         :: "r"(db), "l"(gbp) : "memory");                     \
        }                                                                      \
        asm volatile("cp.async.commit_group;" ::: "memory");                   \
    } while (0)

    STAGE(0, 0);
    for (int ch = 0; ch < 8; ++ch) {
        if (ch + 1 < 8) {
            STAGE((ch + 1) & 1, ch + 1);
            asm volatile("cp.async.wait_group 1;" ::: "memory");
        } else {
            asm volatile("cp.async.wait_group 0;" ::: "memory");
        }
        __syncthreads();

        const uint32_t aT = sb + (ch & 1) * STAGE_SZ;
        const uint32_t bT = aT + 16384;
        #pragma unroll
        for (int ks = 0; ks < 4; ++ks) {
            uint32_t b[8][2];
            #pragma unroll
            for (int nt = 0; nt < 4; ++nt) {
                int brow = wn * 64 + nt * 16 + (grp >> 1) * 8 + lr;
                int sec = ks * 2 + (grp & 1);
                uint32_t bd = bT + brow * 128 + ((sec ^ (brow & 7)) * 16);
                ldmx4(b[2 * nt][0], b[2 * nt][1], b[2 * nt + 1][0],
                      b[2 * nt + 1][1], bd);
            }
            #pragma unroll
            for (int mi = 0; mi < 4; ++mi) {
                uint32_t a[4];
                int arow = wm * 64 + mi * 16 + (grp & 1) * 8 + lr;
                int sec = ks * 2 + (grp >> 1);
                uint32_t ad = aT + arow * 128 + ((sec ^ (arow & 7)) * 16);
                ldmx4(a[0], a[1], a[2], a[3], ad);
                #pragma unroll
                for (int ni = 0; ni < 8; ++ni)
                    mma16816(acc[mi][ni], a, b[ni]);
            }
        }
        __syncthreads();
    }
    #undef STAGE

    // ---- epilogue: per-tile top-2 (values + BOTH indices), both dirs ------
    char* eb = dsmem;
    float* eRV1 = reinterpret_cast<float*>(eb);             // [4][128]
    float* eRV2 = reinterpret_cast<float*>(eb + 2048);
    int*   eRI1 = reinterpret_cast<int*>  (eb + 4096);
    int*   eRI2 = reinterpret_cast<int*>  (eb + 6144);
    float* eCV1 = reinterpret_cast<float*>(eb + 8192);      // [2][256]
    float* eCV2 = reinterpret_cast<float*>(eb + 10240);
    int*   eCI1 = reinterpret_cast<int*>  (eb + 12288);
    int*   eCI2 = reinterpret_cast<int*>  (eb + 14336);

    // rows (A->B): each (mi,h) is one row per thread-quad
    #pragma unroll
    for (int mi = 0; mi < 4; ++mi) {
        #pragma unroll
        for (int h = 0; h < 2; ++h) {
            int row = wm * 64 + mi * 16 + h * 8 + gq;
            float v1 = -3.f, v2 = -3.f; int i1 = 0, i2 = 0;
            #pragma unroll
            for (int ni = 0; ni < 8; ++ni)
                #pragma unroll
                for (int p2 = 0; p2 < 2; ++p2) {
                    float v = acc[mi][ni][h * 2 + p2];
                    int col = j0 + wn * 64 + ni * 8 + 2 * tq + p2;
                    if (v > v1) { v2 = v1; i2 = i1; v1 = v; i1 = col; }
                    else if (v > v2) { v2 = v; i2 = col; }
                }
            #pragma unroll
            for (int m = 1; m <= 2; m <<= 1) {
                float w1 = __shfl_xor_sync(0xffffffffu, v1, m);
                float w2 = __shfl_xor_sync(0xffffffffu, v2, m);
                int   j1 = __shfl_xor_sync(0xffffffffu, i1, m);
                int   j2 = __shfl_xor_sync(0xffffffffu, i2, m);
                merge22(v1, i1, v2, i2, w1, j1, w2, j2);
            }
            if (tq == 0) {
                eRV1[wn * 128 + row] = v1; eRV2[wn * 128 + row] = v2;
                eRI1[wn * 128 + row] = i1; eRI2[wn * 128 + row] = i2;
            }
        }
    }
    // cols (B->A): each (ni,p2) is one col per thread-octet
    #pragma unroll
    for (int ni = 0; ni < 8; ++ni) {
        #pragma unroll
        for (int p2 = 0; p2 < 2; ++p2) {
            int colL = wn * 64 + ni * 8 + 2 * tq + p2;
            float v1 = -3.f, v2 = -3.f; int i1 = 0, i2 = 0;
            #pragma unroll
            for (int mi = 0; mi < 4; ++mi)
                #pragma unroll
                for (int h = 0; h < 2; ++h) {
                    float v = acc[mi][ni][h * 2 + p2];
                    int row = i0 + wm * 64 + mi * 16 + h * 8 + gq;
                    if (v > v1) { v2 = v1; i2 = i1; v1 = v; i1 = row; }
                    else if (v > v2) { v2 = v; i2 = row; }
                }
            #pragma unroll
            for (int m = 4; m <= 16; m <<= 1) {
                float w1 = __shfl_xor_sync(0xffffffffu, v1, m);
                float w2 = __shfl_xor_sync(0xffffffffu, v2, m);
                int   j1 = __shfl_xor_sync(0xffffffffu, i1, m);
                int   j2 = __shfl_xor_sync(0xffffffffu, i2, m);
                merge22(v1, i1, v2, i2, w1, j1, w2, j2);
            }
            if (gq == 0) {
                eCV1[wm * 256 + colL] = v1; eCV2[wm * 256 + colL] = v2;
                eCI1[wm * 256 + colL] = i1; eCI2[wm * 256 + colL] = i2;
            }
        }
    }
    __syncthreads();
    if (tid < 128) {
        float v1 = eRV1[tid], v2 = eRV2[tid]; int i1 = eRI1[tid], i2 = eRI2[tid];
        #pragma unroll
        for (int s = 1; s < 4; ++s)
            merge22(v1, i1, v2, i2, eRV1[s * 128 + tid], eRI1[s * 128 + tid],
                    eRV2[s * 128 + tid], eRI2[s * 128 + tid]);
        size_t ro = (size_t)jT * N_DESC + i0 + tid;
        g_rowV1[ro] = v1; g_rowV2[ro] = v2; g_rowI1[ro] = i1; g_rowI2[ro] = i2;
    }
    {
        float c1 = eCV1[tid], c2 = eCV2[tid]; int ci1 = eCI1[tid], ci2 = eCI2[tid];
        merge22(c1, ci1, c2, ci2, eCV1[256 + tid], eCI1[256 + tid],
                eCV2[256 + tid], eCI2[256 + tid]);
        size_t co = (size_t)iT * N_DESC + j0 + tid;
        g_colV1[co] = c1; g_colV2[co] = c2; g_colI1[co] = ci1; g_colI2[co] = ci2;
    }
}

// ---- kernel 4: level-1 merge into 8 groups per dir ------------------------
__global__ void reduce1_kernel() {
    int i = blockIdx.x * blockDim.x + threadIdx.x;
    if (i >= N_DESC) return;
    int g = blockIdx.y;           // 0..7
    int dir = blockIdx.z;         // 0: rows (48 tiles, 6/group), 1: cols (96, 12/group)
    const float* V1 = dir ? g_colV1 : g_rowV1;
    const float* V2 = dir ? g_colV2 : g_rowV2;
    const int*   I1 = dir ? g_colI1 : g_rowI1;
    const int*   I2 = dir ? g_colI2 : g_rowI2;
    const int cnt = dir ? 12 : 6;
    float v1 = -3.f, v2 = -3.f; int i1 = 0, i2 = 0;
    for (int t = 0; t < cnt; ++t) {
        size_t o = (size_t)(g * cnt + t) * N_DESC + i;
        merge22(v1, i1, v2, i2, V1[o], I1[o], V2[o], I2[o]);
    }
    size_t o = (size_t)(dir * 8 + g) * N_DESC + i;
    g_l1V1[o] = v1; g_l1V2[o] = v2; g_l1I1[o] = i1; g_l1I2[o] = i2;
}

// ---- kernel 5: merge 8 groups -> 4 candidates per row/col -----------------
__global__ void cand_kernel() {
    int i = blockIdx.x * blockDim.x + threadIdx.x;
    if (i >= N_DESC) return;
    int dir = blockIdx.y;
    float cv[4] = {-4.f, -4.f, -4.f, -4.f};
    int   ci[4] = {0, 0, 0, 0};
    for (int g = 0; g < 8; ++g) {
        size_t o = (size_t)(dir * 8 + g) * N_DESC + i;
        #pragma unroll
        for (int e = 0; e < 2; ++e) {
            float v = e ? g_l1V2[o] : g_l1V1[o];
            int   ix = e ? g_l1I2[o] : g_l1I1[o];
            if (v > cv[3] || (v == cv[3] && ix < ci[3])) {
                cv[3] = v; ci[3] = ix;
                #pragma unroll
                for (int q = 3; q > 0; --q)
                    if (cv[q] > cv[q - 1] ||
                        (cv[q] == cv[q - 1] && ci[q] < ci[q - 1])) {
                        float tv = cv[q]; cv[q] = cv[q - 1]; cv[q - 1] = tv;
                        int ti = ci[q]; ci[q] = ci[q - 1]; ci[q - 1] = ti;
                    }
            }
        }
    }
    #pragma unroll
    for (int q = 0; q < 4; ++q)
        g_cI[((size_t)dir * 4 + q) * N_DESC + i] = ci[q];
}

// ---- kernel 6: fp32 rescore of 4 candidates (one warp per row/col) --------
__global__ void rescore_kernel() {
    const int lane = threadIdx.x & 31;
    const int w = threadIdx.x >> 5;
    const int row = blockIdx.x * 8 + w;
    const int dir = blockIdx.y;
    if (row >= N_DESC) return;
    const float* X = dir ? g_fB : g_fA;
    const float* Y = dir ? g_fA : g_fB;
    int idx[4];
    #pragma unroll
    for (int q = 0; q < 4; ++q)
        idx[q] = g_cI[((size_t)dir * 4 + q) * N_DESC + row];
    float s[4] = {0.f, 0.f, 0.f, 0.f};
    const float4* xr = reinterpret_cast<const float4*>(X + (size_t)row * CH) + lane * 4;
    #pragma unroll
    for (int u = 0; u < 4; ++u) {
        float4 xa = xr[u];
        #pragma unroll
        for (int q = 0; q < 4; ++q) {
            float4 yb = *(reinterpret_cast<const float4*>(Y + (size_t)idx[q] * CH) +
                          lane * 4 + u);
            s[q] += xa.x * yb.x + xa.y * yb.y + xa.z * yb.z + xa.w * yb.w;
        }
    }
    #pragma unroll
    for (int m = 16; m > 0; m >>= 1)
        #pragma unroll
        for (int q = 0; q < 4; ++q)
            s[q] += __shfl_xor_sync(0xffffffffu, s[q], m);
    if (lane == 0) {
        float v1 = -4.f, v2 = -4.f; int i1 = 0;
        #pragma unroll
        for (int q = 0; q < 4; ++q) {
            if (s[q] > v1 || (s[q] == v1 && idx[q] < i1)) {
                v2 = v1; v1 = s[q]; i1 = idx[q];
            } else if (s[q] > v2) v2 = s[q];
        }
        if (dir == 0) { g_aV1[row] = v1; g_aV2[row] = v2; g_aI1[row] = i1; }
        else          { g_bV1[row] = v1; g_bV2[row] = v2; g_bI1[row] = i1; }
    }
}

// ---- kernel 7: mutual check + ratio test + output -------------------------
__global__ void match_kernel(float* __restrict__ out) {
    int i = blockIdx.x * blockDim.x + threadIdx.x;
    if (i >= N_DESC) return;
    float s1 = g_aV1[i], s2 = g_aV2[i];
    int   n12 = g_aI1[i];
    float r12 = (2.0f - 2.0f * s1) / (2.0f - 2.0f * s2 + EPS_T);
    int   n21 = g_bI1[n12];
    float r21 = (2.0f - 2.0f * g_bV1[n12]) / (2.0f - 2.0f * g_bV2[n12] + EPS_T);
    bool mask = (n21 == i) && (r12 <= RATIO_T) && (r21 <= RATIO_T);
    out[i]              = mask ? s1 : 0.0f;
    out[N_DESC + i]     = (float)n12;
    out[2 * N_DESC + i] = mask ? 1.0f : 0.0f;
}

// ---------------------------------------------------------------------------
extern "C" void kernel_launch(void* const* d_in, const int* in_sizes, int n_in,
                              void* d_out, int out_size) {
    const float* mA = (const float*)d_in[0];
    const float* mB = (const float*)d_in[1];
    float* out = (float*)d_out;

    cudaFuncSetAttribute(gemm_top2_kernel,
                         cudaFuncAttributeMaxDynamicSharedMemorySize, SMEM_GEMM);

    dim3 nb(N_DESC / 256, 2);
    norms_kernel<<<nb, 256>>>(mA, mB);

    dim3 pp(N_DESC / 64, CH / 64, 2);
    prep_kernel<<<pp, 256>>>(mA, mB);

    dim3 gb(NTI, NTJ);
    gemm_top2_kernel<<<gb, 256, SMEM_GEMM>>>();

    dim3 r1(N_DESC / 256, 8, 2);
    reduce1_kernel<<<r1, 256>>>();

    dim3 cd(N_DESC / 256, 2);
    cand_kernel<<<cd, 256>>>();

    dim3 rs(N_DESC / 8, 2);
    rescore_kernel<<<rs, 256>>>();

    match_kernel<<<N_DESC / 256, 256>>>(out);
}

// round 8
// speedup vs baseline: 1.1708x; 1.1708x over previous
#include <cuda_runtime.h>
#include <cuda_bf16.h>
#include <cuda_fp8.h>
#include <cstdint>

// ---------------------------------------------------------------------------
// DeepFeatureMatcher: fp8-e4m3 mma.sync screening GEMM (CTA 128x128, warp
// 32x64, cp.async double buffer) -> per-tile bidirectional top-2 ->
// merge to 8 candidates -> exact fp32 rescore -> mutual + ratio test.
// Output (float32, 3*12288): [masked_sim | nn12 as float | mask as 0/1]
// ---------------------------------------------------------------------------

#define N_DESC 12288
#define CH     512
#define NT     96                    // 128-wide tiles per dim
#define NCAND  8
#define FP8_SCALE 64.0f
#define RATIO_T 0.95f
#define EPS_T   1e-8f
#define STAGE_SZ 32768               // 16KB A + 16KB B per stage (fp8)
#define SMEM_GEMM (2 * STAGE_SZ)
#define NEG_INF (-1e30f)

// ---- device global scratch (no allocation allowed) ------------------------
__device__ __align__(256) float   g_fA[N_DESC * CH];   // normalized fp32, desc-major
__device__ __align__(256) float   g_fB[N_DESC * CH];
__device__ __align__(256) uint8_t g_qA[N_DESC * CH];   // e4m3 (x64), desc-major
__device__ __align__(256) uint8_t g_qB[N_DESC * CH];
__device__ float g_rnA[N_DESC], g_rnB[N_DESC];
// per-tile top2 partials (scaled sims): rows [jT][N], cols [iT][N]
__device__ float g_rowV1[NT * N_DESC], g_rowV2[NT * N_DESC];
__device__ int   g_rowI1[NT * N_DESC], g_rowI2[NT * N_DESC];
__device__ float g_colV1[NT * N_DESC], g_colV2[NT * N_DESC];
__device__ int   g_colI1[NT * N_DESC], g_colI2[NT * N_DESC];
// level-1 merged (8 groups of 12 tiles), per dir
__device__ float g_l1V1[2 * 8 * N_DESC], g_l1V2[2 * 8 * N_DESC];
__device__ int   g_l1I1[2 * 8 * N_DESC], g_l1I2[2 * 8 * N_DESC];
// NCAND candidates per row/col, per dir
__device__ int   g_cI[2 * NCAND * N_DESC];
// rescored fp32 top-2
__device__ float g_aV1[N_DESC], g_aV2[N_DESC]; __device__ int g_aI1[N_DESC];
__device__ float g_bV1[N_DESC], g_bV2[N_DESC]; __device__ int g_bI1[N_DESC];

// ---- helpers --------------------------------------------------------------
__device__ __forceinline__ uint32_t smem_u32(const void* p) {
    uint32_t a;
    asm("{ .reg .u64 t; cvta.to.shared.u64 t, %1; cvt.u32.u64 %0, t; }"
        : "=r"(a) : "l"(p));
    return a;
}
__device__ __forceinline__ void ldmx4(uint32_t& r0, uint32_t& r1,
                                      uint32_t& r2, uint32_t& r3, uint32_t addr) {
    asm volatile("ldmatrix.sync.aligned.m8n8.x4.shared.b16 {%0,%1,%2,%3}, [%4];"
                 : "=r"(r0), "=r"(r1), "=r"(r2), "=r"(r3) : "r"(addr));
}
__device__ __forceinline__ void mma_fp8(float* c, const uint32_t* a,
                                        const uint32_t* b) {
    asm volatile(
        "mma.sync.aligned.m16n8k32.row.col.f32.e4m3.e4m3.f32 "
        "{%0,%1,%2,%3}, {%4,%5,%6,%7}, {%8,%9}, {%0,%1,%2,%3};"
        : "+f"(c[0]), "+f"(c[1]), "+f"(c[2]), "+f"(c[3])
        : "r"(a[0]), "r"(a[1]), "r"(a[2]), "r"(a[3]), "r"(b[0]), "r"(b[1]));
}
// merge top-2 list (w1,j1,w2,j2) into (v1,i1,v2,i2); lower index wins ties
__device__ __forceinline__ void merge22(float& v1, int& i1, float& v2, int& i2,
                                        float w1, int j1, float w2, int j2) {
    if (w1 > v1 || (w1 == v1 && j1 < i1)) {
        if (v1 > w2 || (v1 == w2 && i1 < j2)) { v2 = v1; i2 = i1; }
        else                                   { v2 = w2; i2 = j2; }
        v1 = w1; i1 = j1;
    } else if (w1 > v2 || (w1 == v2 && j1 < i2)) {
        v2 = w1; i2 = j1;
    }
}

// ---- kernel 1: inverse norms ----------------------------------------------
__global__ void norms_kernel(const float* __restrict__ mA,
                             const float* __restrict__ mB) {
    int i = blockIdx.x * blockDim.x + threadIdx.x;
    if (i >= N_DESC) return;
    const float* m = blockIdx.y ? mB : mA;
    float s = 0.f;
    #pragma unroll 8
    for (int c = 0; c < CH; ++c) {
        float v = m[(size_t)c * N_DESC + i];
        s = fmaf(v, v, s);
    }
    float r = 1.0f / sqrtf(s);
    if (blockIdx.y) g_rnB[i] = r; else g_rnA[i] = r;
}

// ---- kernel 2: normalize + transpose -> fp32 and e4m3(x64) desc-major -----
__global__ void prep_kernel(const float* __restrict__ mA,
                            const float* __restrict__ mB) {
    __shared__ float t[64][65];
    const int tid = threadIdx.x;
    const int i0 = blockIdx.x * 64;
    const int c0 = blockIdx.y * 64;
    const float* m = blockIdx.z ? mB : mA;
    const float* rn = blockIdx.z ? g_rnB : g_rnA;
    float* gf = blockIdx.z ? g_fB : g_fA;
    uint8_t* gq = blockIdx.z ? g_qB : g_qA;

    const int ii = tid & 63, cb = tid >> 6;
    #pragma unroll
    for (int it = 0; it < 16; ++it) {
        int cc = it * 4 + cb;
        t[cc][ii] = m[(size_t)(c0 + cc) * N_DESC + i0 + ii] * rn[i0 + ii];
    }
    __syncthreads();

    const int cc2 = tid & 31, rw = tid >> 5;
    #pragma unroll
    for (int it = 0; it < 8; ++it) {
        int i = rw + it * 8;
        float v0 = t[2 * cc2][i], v1 = t[2 * cc2 + 1][i];
        size_t base = (size_t)(i0 + i) * CH + c0 + 2 * cc2;
        *reinterpret_cast<float2*>(&gf[base]) = make_float2(v0, v1);
        uint8_t q0 = (uint8_t)__nv_cvt_float_to_fp8(v0 * FP8_SCALE, __NV_SATFINITE, __NV_E4M3);
        uint8_t q1 = (uint8_t)__nv_cvt_float_to_fp8(v1 * FP8_SCALE, __NV_SATFINITE, __NV_E4M3);
        *reinterpret_cast<uint16_t*>(&gq[base]) = (uint16_t)(q0 | (q1 << 8));
    }
}

// ---- kernel 3: fp8 screening GEMM (128x128 tile) + per-tile top-2 ---------
// SMEM rows: 128 bytes of fp8 (k-chunk 128 elems), SW128 swizzle; the fp8
// m16n8k32 fragments map onto the same ldmatrix sector addressing as bf16.
extern __shared__ char dsmem[];
__global__ __launch_bounds__(256, 2) void gemm_top2_kernel() {
    const int tid = threadIdx.x;
    const int wid = tid >> 5, lane = tid & 31;
    const int wm = wid >> 1, wn = wid & 1;     // warp tile: 32 rows x 64 cols
    const int grp = lane >> 3, lr = lane & 7;
    const int gq = lane >> 2, tq = lane & 3;
    const int iT = blockIdx.x, jT = blockIdx.y;
    const int i0 = iT * 128, j0 = jT * 128;
    const uint32_t sb = smem_u32(dsmem);

    float acc[2][8][4];
    #pragma unroll
    for (int mi = 0; mi < 2; ++mi)
        #pragma unroll
        for (int ni = 0; ni < 8; ++ni)
            #pragma unroll
            for (int c = 0; c < 4; ++c) acc[mi][ni][c] = 0.f;

    const int r0 = tid >> 3;       // staging row 0..31
    const int c8 = tid & 7;        // 16B sector
    const uint32_t swb = (uint32_t)r0 * 128 + c8 * 16;
    const uint32_t swo = swb ^ ((swb >> 3) & 0x70);

    // ---- cp.async staging of one (A,B) 128x128B fp8 chunk pair ------------
    #define STAGE(buf, chn) do {                                               \
        const size_t kof = (size_t)(chn) * 128 + c8 * 16;                      \
        _Pragma("unroll")                                                      \
        for (int it = 0; it < 4; ++it) {                                       \
            const uint8_t* ga = g_qA + (size_t)(i0 + r0 + it * 32) * CH + kof; \
            uint32_t da = sb + (buf) * STAGE_SZ + it * 4096 + swo;             \
            asm volatile("cp.async.cg.shared.global [%0], [%1], 16;"           \
                         :: "r"(da), "l"(ga) : "memory");                      \
            const uint8_t* gbp = g_qB + (size_t)(j0 + r0 + it * 32) * CH + kof;\
            uint32_t db = sb + (buf) * STAGE_SZ + 16384 + it * 4096 + swo;     \
            asm volatile("cp.async.cg.shared.global [%0], [%1], 16;"           \
                         :: "r"(db), "l"(gbp) : "memory");                     \
        }                                                                      \
        asm volatile("cp.async.commit_group;" ::: "memory");                   \
    } while (0)

    STAGE(0, 0);
    for (int ch = 0; ch < 4; ++ch) {
        if (ch + 1 < 4) {
            STAGE((ch + 1) & 1, ch + 1);
            asm volatile("cp.async.wait_group 1;" ::: "memory");
        } else {
            asm volatile("cp.async.wait_group 0;" ::: "memory");
        }
        __syncthreads();

        const uint32_t aT = sb + (ch & 1) * STAGE_SZ;
        const uint32_t bT = aT + 16384;
        #pragma unroll
        for (int ks = 0; ks < 4; ++ks) {      // 4 x k32 fp8 steps per 128B chunk
            uint32_t a[2][4];
            #pragma unroll
            for (int mi = 0; mi < 2; ++mi) {
                int arow = wm * 32 + mi * 16 + (grp & 1) * 8 + lr;
                int sec = ks * 2 + (grp >> 1);
                uint32_t ad = aT + arow * 128 + ((sec ^ (arow & 7)) * 16);
                ldmx4(a[mi][0], a[mi][1], a[mi][2], a[mi][3], ad);
            }
            uint32_t b[8][2];
            #pragma unroll
            for (int nt = 0; nt < 4; ++nt) {
                int brow = wn * 64 + nt * 16 + (grp >> 1) * 8 + lr;
                int sec = ks * 2 + (grp & 1);
                uint32_t bd = bT + brow * 128 + ((sec ^ (brow & 7)) * 16);
                ldmx4(b[2 * nt][0], b[2 * nt][1], b[2 * nt + 1][0],
                      b[2 * nt + 1][1], bd);
            }
            #pragma unroll
            for (int mi = 0; mi < 2; ++mi)
                #pragma unroll
                for (int ni = 0; ni < 8; ++ni)
                    mma_fp8(acc[mi][ni], a[mi], b[ni]);
        }
        __syncthreads();
    }
    #undef STAGE

    // ---- epilogue: per-tile top-2 (values + BOTH indices), both dirs ------
    char* eb = dsmem;
    float* eRV1 = reinterpret_cast<float*>(eb);             // [2][128]
    float* eRV2 = reinterpret_cast<float*>(eb + 1024);
    int*   eRI1 = reinterpret_cast<int*>  (eb + 2048);
    int*   eRI2 = reinterpret_cast<int*>  (eb + 3072);
    float* eCV1 = reinterpret_cast<float*>(eb + 4096);      // [4][128]
    float* eCV2 = reinterpret_cast<float*>(eb + 6144);
    int*   eCI1 = reinterpret_cast<int*>  (eb + 8192);
    int*   eCI2 = reinterpret_cast<int*>  (eb + 10240);

    // rows (A->B)
    #pragma unroll
    for (int mi = 0; mi < 2; ++mi) {
        #pragma unroll
        for (int h = 0; h < 2; ++h) {
            int row = wm * 32 + mi * 16 + h * 8 + gq;
            float v1 = NEG_INF, v2 = NEG_INF; int i1 = 0, i2 = 0;
            #pragma unroll
            for (int ni = 0; ni < 8; ++ni)
                #pragma unroll
                for (int p2 = 0; p2 < 2; ++p2) {
                    float v = acc[mi][ni][h * 2 + p2];
                    int col = j0 + wn * 64 + ni * 8 + 2 * tq + p2;
                    if (v > v1) { v2 = v1; i2 = i1; v1 = v; i1 = col; }
                    else if (v > v2) { v2 = v; i2 = col; }
                }
            #pragma unroll
            for (int m = 1; m <= 2; m <<= 1) {
                float w1 = __shfl_xor_sync(0xffffffffu, v1, m);
                float w2 = __shfl_xor_sync(0xffffffffu, v2, m);
                int   j1 = __shfl_xor_sync(0xffffffffu, i1, m);
                int   j2 = __shfl_xor_sync(0xffffffffu, i2, m);
                merge22(v1, i1, v2, i2, w1, j1, w2, j2);
            }
            if (tq == 0) {
                eRV1[wn * 128 + row] = v1; eRV2[wn * 128 + row] = v2;
                eRI1[wn * 128 + row] = i1; eRI2[wn * 128 + row] = i2;
            }
        }
    }
    // cols (B->A)
    #pragma unroll
    for (int ni = 0; ni < 8; ++ni) {
        #pragma unroll
        for (int p2 = 0; p2 < 2; ++p2) {
            int colL = wn * 64 + ni * 8 + 2 * tq + p2;
            float v1 = NEG_INF, v2 = NEG_INF; int i1 = 0, i2 = 0;
            #pragma unroll
            for (int mi = 0; mi < 2; ++mi)
                #pragma unroll
                for (int h = 0; h < 2; ++h) {
                    float v = acc[mi][ni][h * 2 + p2];
                    int row = i0 + wm * 32 + mi * 16 + h * 8 + gq;
                    if (v > v1) { v2 = v1; i2 = i1; v1 = v; i1 = row; }
                    else if (v > v2) { v2 = v; i2 = row; }
                }
            #pragma unroll
            for (int m = 4; m <= 16; m <<= 1) {
                float w1 = __shfl_xor_sync(0xffffffffu, v1, m);
                float w2 = __shfl_xor_sync(0xffffffffu, v2, m);
                int   j1 = __shfl_xor_sync(0xffffffffu, i1, m);
                int   j2 = __shfl_xor_sync(0xffffffffu, i2, m);
                merge22(v1, i1, v2, i2, w1, j1, w2, j2);
            }
            if (gq == 0) {
                eCV1[wm * 128 + colL] = v1; eCV2[wm * 128 + colL] = v2;
                eCI1[wm * 128 + colL] = i1; eCI2[wm * 128 + colL] = i2;
            }
        }
    }
    __syncthreads();
    if (tid < 128) {
        float v1 = eRV1[tid], v2 = eRV2[tid]; int i1 = eRI1[tid], i2 = eRI2[tid];
        merge22(v1, i1, v2, i2, eRV1[128 + tid], eRI1[128 + tid],
                eRV2[128 + tid], eRI2[128 + tid]);
        size_t ro = (size_t)jT * N_DESC + i0 + tid;
        g_rowV1[ro] = v1; g_rowV2[ro] = v2; g_rowI1[ro] = i1; g_rowI2[ro] = i2;

        float c1 = eCV1[tid], c2 = eCV2[tid]; int ci1 = eCI1[tid], ci2 = eCI2[tid];
        #pragma unroll
        for (int g2 = 1; g2 < 4; ++g2)
            merge22(c1, ci1, c2, ci2, eCV1[g2 * 128 + tid], eCI1[g2 * 128 + tid],
                    eCV2[g2 * 128 + tid], eCI2[g2 * 128 + tid]);
        size_t co = (size_t)iT * N_DESC + j0 + tid;
        g_colV1[co] = c1; g_colV2[co] = c2; g_colI1[co] = ci1; g_colI2[co] = ci2;
    }
}

// ---- kernel 4: level-1 merge (12 tiles per group, 8 groups, both dirs) ----
__global__ void reduce1_kernel() {
    int i = blockIdx.x * blockDim.x + threadIdx.x;
    if (i >= N_DESC) return;
    int g = blockIdx.y;           // 0..7
    int dir = blockIdx.z;         // 0: rows, 1: cols
    const float* V1 = dir ? g_colV1 : g_rowV1;
    const float* V2 = dir ? g_colV2 : g_rowV2;
    const int*   I1 = dir ? g_colI1 : g_rowI1;
    const int*   I2 = dir ? g_colI2 : g_rowI2;
    float v1 = NEG_INF, v2 = NEG_INF; int i1 = 0, i2 = 0;
    for (int t = 0; t < 12; ++t) {
        size_t o = (size_t)(g * 12 + t) * N_DESC + i;
        merge22(v1, i1, v2, i2, V1[o], I1[o], V2[o], I2[o]);
    }
    size_t o = (size_t)(dir * 8 + g) * N_DESC + i;
    g_l1V1[o] = v1; g_l1V2[o] = v2; g_l1I1[o] = i1; g_l1I2[o] = i2;
}

// ---- kernel 5: merge 8 groups -> NCAND candidates per row/col -------------
__global__ void cand_kernel() {
    int i = blockIdx.x * blockDim.x + threadIdx.x;
    if (i >= N_DESC) return;
    int dir = blockIdx.y;
    float cv[NCAND]; int ci[NCAND];
    #pragma unroll
    for (int q = 0; q < NCAND; ++q) { cv[q] = NEG_INF; ci[q] = 0; }
    for (int g = 0; g < 8; ++g) {
        size_t o = (size_t)(dir * 8 + g) * N_DESC + i;
        #pragma unroll
        for (int e = 0; e < 2; ++e) {
            float v = e ? g_l1V2[o] : g_l1V1[o];
            int   ix = e ? g_l1I2[o] : g_l1I1[o];
            if (v > cv[NCAND - 1] || (v == cv[NCAND - 1] && ix < ci[NCAND - 1])) {
                cv[NCAND - 1] = v; ci[NCAND - 1] = ix;
                #pragma unroll
                for (int q = NCAND - 1; q > 0; --q)
                    if (cv[q] > cv[q - 1] ||
                        (cv[q] == cv[q - 1] && ci[q] < ci[q - 1])) {
                        float tv = cv[q]; cv[q] = cv[q - 1]; cv[q - 1] = tv;
                        int ti = ci[q]; ci[q] = ci[q - 1]; ci[q - 1] = ti;
                    }
            }
        }
    }
    #pragma unroll
    for (int q = 0; q < NCAND; ++q)
        g_cI[((size_t)dir * NCAND + q) * N_DESC + i] = ci[q];
}

// ---- kernel 6: fp32 rescore of NCAND candidates (one warp per row/col) ----
__global__ void rescore_kernel() {
    const int lane = threadIdx.x & 31;
    const int w = threadIdx.x >> 5;
    const int row = blockIdx.x * 8 + w;
    const int dir = blockIdx.y;
    if (row >= N_DESC) return;
    const float* X = dir ? g_fB : g_fA;
    const float* Y = dir ? g_fA : g_fB;
    int idx[NCAND];
    #pragma unroll
    for (int q = 0; q < NCAND; ++q)
        idx[q] = g_cI[((size_t)dir * NCAND + q) * N_DESC + row];
    float s[NCAND];
    #pragma unroll
    for (int q = 0; q < NCAND; ++q) s[q] = 0.f;
    const float4* xr = reinterpret_cast<const float4*>(X + (size_t)row * CH) + lane * 4;
    #pragma unroll
    for (int u = 0; u < 4; ++u) {
        float4 xa = xr[u];
        #pragma unroll
        for (int q = 0; q < NCAND; ++q) {
            float4 yb = *(reinterpret_cast<const float4*>(Y + (size_t)idx[q] * CH) +
                          lane * 4 + u);
            s[q] += xa.x * yb.x + xa.y * yb.y + xa.z * yb.z + xa.w * yb.w;
        }
    }
    #pragma unroll
    for (int m = 16; m > 0; m >>= 1)
        #pragma unroll
        for (int q = 0; q < NCAND; ++q)
            s[q] += __shfl_xor_sync(0xffffffffu, s[q], m);
    if (lane == 0) {
        float v1 = NEG_INF, v2 = NEG_INF; int i1 = 0;
        #pragma unroll
        for (int q = 0; q < NCAND; ++q) {
            if (s[q] > v1 || (s[q] == v1 && idx[q] < i1)) {
                v2 = v1; v1 = s[q]; i1 = idx[q];
            } else if (s[q] > v2) v2 = s[q];
        }
        if (dir == 0) { g_aV1[row] = v1; g_aV2[row] = v2; g_aI1[row] = i1; }
        else          { g_bV1[row] = v1; g_bV2[row] = v2; g_bI1[row] = i1; }
    }
}

// ---- kernel 7: mutual check + ratio test + output -------------------------
__global__ void match_kernel(float* __restrict__ out) {
    int i = blockIdx.x * blockDim.x + threadIdx.x;
    if (i >= N_DESC) return;
    float s1 = g_aV1[i], s2 = g_aV2[i];
    int   n12 = g_aI1[i];
    float r12 = (2.0f - 2.0f * s1) / (2.0f - 2.0f * s2 + EPS_T);
    int   n21 = g_bI1[n12];
    float r21 = (2.0f - 2.0f * g_bV1[n12]) / (2.0f - 2.0f * g_bV2[n12] + EPS_T);
    bool mask = (n21 == i) && (r12 <= RATIO_T) && (r21 <= RATIO_T);
    out[i]              = mask ? s1 : 0.0f;
    out[N_DESC + i]     = (float)n12;
    out[2 * N_DESC + i] = mask ? 1.0f : 0.0f;
}

// ---------------------------------------------------------------------------
extern "C" void kernel_launch(void* const* d_in, const int* in_sizes, int n_in,
                              void* d_out, int out_size) {
    const float* mA = (const float*)d_in[0];
    const float* mB = (const float*)d_in[1];
    float* out = (float*)d_out;

    cudaFuncSetAttribute(gemm_top2_kernel,
                         cudaFuncAttributeMaxDynamicSharedMemorySize, SMEM_GEMM);

    dim3 nb(N_DESC / 256, 2);
    norms_kernel<<<nb, 256>>>(mA, mB);

    dim3 pp(N_DESC / 64, CH / 64, 2);
    prep_kernel<<<pp, 256>>>(mA, mB);

    dim3 gb(NT, NT);
    gemm_top2_kernel<<<gb, 256, SMEM_GEMM>>>();

    dim3 r1(N_DESC / 256, 8, 2);
    reduce1_kernel<<<r1, 256>>>();

    dim3 cd(N_DESC / 256, 2);
    cand_kernel<<<cd, 256>>>();

    dim3 rs(N_DESC / 8, 2);
    rescore_kernel<<<rs, 256>>>();

    match_kernel<<<N_DESC / 256, 256>>>(out);
}

// round 11
// speedup vs baseline: 1.2386x; 1.0579x over previous
#include <cuda_runtime.h>
#include <cuda_bf16.h>
#include <cstdint>

// ---------------------------------------------------------------------------
// DeepFeatureMatcher: bf16 mma.sync screening GEMM (fused bidirectional
// per-tile top-2 with indices) -> single-pass merge to 4 candidates per
// row/col -> exact fp32 rescore of candidates -> mutual + ratio test.
// Output (float32, 3*12288): [masked_sim | nn12 as float | mask as 0/1]
// ---------------------------------------------------------------------------

#define N_DESC 12288
#define CH     512
#define NT     96                    // 128-wide tiles per dim
#define NCAND  4
#define RATIO_T 0.95f
#define EPS_T   1e-8f
#define SMEM_GEMM 65536              // 2 x (16KB A + 16KB B) double buffer
#define NEG_INF (-1e30f)

// ---- device global scratch (no allocation allowed) ------------------------
__device__ __align__(256) float         g_fA[N_DESC * CH];  // normalized fp32, desc-major
__device__ __align__(256) float         g_fB[N_DESC * CH];
__device__ __align__(256) __nv_bfloat16 g_bA[N_DESC * CH];  // normalized bf16, desc-major
__device__ __align__(256) __nv_bfloat16 g_bB[N_DESC * CH];
__device__ float g_rnA[N_DESC], g_rnB[N_DESC];
// per-tile top2 partials (both indices), rows: [jT][N], cols: [iT][N]
__device__ float g_rowV1[NT * N_DESC], g_rowV2[NT * N_DESC];
__device__ int   g_rowI1[NT * N_DESC], g_rowI2[NT * N_DESC];
__device__ float g_colV1[NT * N_DESC], g_colV2[NT * N_DESC];
__device__ int   g_colI1[NT * N_DESC], g_colI2[NT * N_DESC];
// NCAND candidates per row/col, per dir
__device__ int   g_cI[2 * NCAND * N_DESC];
// rescored fp32 top-2
__device__ float g_aV1[N_DESC], g_aV2[N_DESC]; __device__ int g_aI1[N_DESC];
__device__ float g_bV1[N_DESC], g_bV2[N_DESC]; __device__ int g_bI1[N_DESC];

// ---- helpers --------------------------------------------------------------
__device__ __forceinline__ uint32_t smem_u32(const void* p) {
    uint32_t a;
    asm("{ .reg .u64 t; cvta.to.shared.u64 t, %1; cvt.u32.u64 %0, t; }"
        : "=r"(a) : "l"(p));
    return a;
}
__device__ __forceinline__ void ldmx4(uint32_t& r0, uint32_t& r1,
                                      uint32_t& r2, uint32_t& r3, uint32_t addr) {
    asm volatile("ldmatrix.sync.aligned.m8n8.x4.shared.b16 {%0,%1,%2,%3}, [%4];"
                 : "=r"(r0), "=r"(r1), "=r"(r2), "=r"(r3) : "r"(addr));
}
__device__ __forceinline__ void mma16816(float* c, const uint32_t* a,
                                         const uint32_t* b) {
    asm volatile(
        "mma.sync.aligned.m16n8k16.row.col.f32.bf16.bf16.f32 "
        "{%0,%1,%2,%3}, {%4,%5,%6,%7}, {%8,%9}, {%0,%1,%2,%3};"
        : "+f"(c[0]), "+f"(c[1]), "+f"(c[2]), "+f"(c[3])
        : "r"(a[0]), "r"(a[1]), "r"(a[2]), "r"(a[3]), "r"(b[0]), "r"(b[1]));
}
// merge top-2 list (w1,j1,w2,j2) into (v1,i1,v2,i2); lower index wins ties
__device__ __forceinline__ void merge22(float& v1, int& i1, float& v2, int& i2,
                                        float w1, int j1, float w2, int j2) {
    if (w1 > v1 || (w1 == v1 && j1 < i1)) {
        if (v1 > w2 || (v1 == w2 && i1 < j2)) { v2 = v1; i2 = i1; }
        else                                   { v2 = w2; i2 = j2; }
        v1 = w1; i1 = j1;
    } else if (w1 > v2 || (w1 == v2 && j1 < i2)) {
        v2 = w1; i2 = j1;
    }
}

// ---- kernel 1: inverse norms ----------------------------------------------
__global__ void norms_kernel(const float* __restrict__ mA,
                             const float* __restrict__ mB) {
    int i = blockIdx.x * blockDim.x + threadIdx.x;
    if (i >= N_DESC) return;
    const float* m = blockIdx.y ? mB : mA;
    float s = 0.f;
    #pragma unroll 8
    for (int c = 0; c < CH; ++c) {
        float v = m[(size_t)c * N_DESC + i];
        s = fmaf(v, v, s);
    }
    float r = 1.0f / sqrtf(s);
    if (blockIdx.y) g_rnB[i] = r; else g_rnA[i] = r;
}

// ---- kernel 2: normalize + transpose -> fp32 and bf16 desc-major ----------
__global__ void prep_kernel(const float* __restrict__ mA,
                            const float* __restrict__ mB) {
    __shared__ float t[64][65];
    const int tid = threadIdx.x;
    const int i0 = blockIdx.x * 64;
    const int c0 = blockIdx.y * 64;
    const float* m = blockIdx.z ? mB : mA;
    const float* rn = blockIdx.z ? g_rnB : g_rnA;
    float* gf = blockIdx.z ? g_fB : g_fA;
    __nv_bfloat16* gb = blockIdx.z ? g_bB : g_bA;

    const int ii = tid & 63, cb = tid >> 6;
    #pragma unroll
    for (int it = 0; it < 16; ++it) {
        int cc = it * 4 + cb;
        t[cc][ii] = m[(size_t)(c0 + cc) * N_DESC + i0 + ii] * rn[i0 + ii];
    }
    __syncthreads();

    const int cc2 = tid & 31, rw = tid >> 5;
    #pragma unroll
    for (int it = 0; it < 8; ++it) {
        int i = rw + it * 8;
        float v0 = t[2 * cc2][i], v1 = t[2 * cc2 + 1][i];
        size_t base = (size_t)(i0 + i) * CH + c0 + 2 * cc2;
        *reinterpret_cast<float2*>(&gf[base]) = make_float2(v0, v1);
        uint32_t pk = ((uint32_t)__bfloat16_as_ushort(__float2bfloat16_rn(v1)) << 16) |
                      (uint32_t)__bfloat16_as_ushort(__float2bfloat16_rn(v0));
        *reinterpret_cast<uint32_t*>(&gb[base]) = pk;
    }
}

// ---- kernel 3: bf16 screening GEMM + per-tile bidirectional top-2 ---------
extern __shared__ char dsmem[];
__global__ __launch_bounds__(256, 2) void gemm_top2_kernel() {
    const int tid = threadIdx.x;
    const int wid = tid >> 5, lane = tid & 31;
    const int wm = wid >> 1, wn = wid & 1;     // warp tile: 32 rows x 64 cols
    const int grp = lane >> 3, lr = lane & 7;
    const int gq = lane >> 2, tq = lane & 3;
    const int iT = blockIdx.x, jT = blockIdx.y;
    const int i0 = iT * 128, j0 = jT * 128;
    const uint32_t sb = smem_u32(dsmem);

    float acc[2][8][4];
    #pragma unroll
    for (int mi = 0; mi < 2; ++mi)
        #pragma unroll
        for (int ni = 0; ni < 8; ++ni)
            #pragma unroll
            for (int c = 0; c < 4; ++c) acc[mi][ni][c] = 0.f;

    const int r0 = tid >> 3;       // staging row 0..31
    const int c8 = tid & 7;        // 16B sector

    // ---- cp.async staging of one (A,B) 128x64 bf16 chunk pair -------------
    #define STAGE(buf, chn) do {                                               \
        const size_t kof = (size_t)(chn) * 64;                                 \
        _Pragma("unroll")                                                      \
        for (int it = 0; it < 4; ++it) {                                       \
            int r = r0 + it * 32;                                              \
            uint32_t off = (uint32_t)r * 128 + c8 * 16;                        \
            uint32_t sw = off ^ ((off >> 3) & 0x70);                           \
            const __nv_bfloat16* ga = g_bA + (size_t)(i0 + r) * CH + kof + c8 * 8; \
            uint32_t da = sb + (buf) * 32768 + sw;                             \
            asm volatile("cp.async.cg.shared.global [%0], [%1], 16;"           \
                         :: "r"(da), "l"(ga) : "memory");                      \
            const __nv_bfloat16* gbp = g_bB + (size_t)(j0 + r) * CH + kof + c8 * 8; \
            uint32_t db = sb + (buf) * 32768 + 16384 + sw;                     \
            asm volatile("cp.async.cg.shared.global [%0], [%1], 16;"           \
                         :: "r"(db), "l"(gbp) : "memory");                     \
        }                                                                      \
        asm volatile("cp.async.commit_group;" ::: "memory");                   \
    } while (0)

    STAGE(0, 0);
    for (int ch = 0; ch < 8; ++ch) {
        if (ch + 1 < 8) {
            STAGE((ch + 1) & 1, ch + 1);
            asm volatile("cp.async.wait_group 1;" ::: "memory");
        } else {
            asm volatile("cp.async.wait_group 0;" ::: "memory");
        }
        __syncthreads();

        const uint32_t aT = sb + (ch & 1) * 32768;
        const uint32_t bT = aT + 16384;
        #pragma unroll
        for (int ks = 0; ks < 4; ++ks) {
            uint32_t a[2][4];
            #pragma unroll
            for (int mi = 0; mi < 2; ++mi) {
                int arow = wm * 32 + mi * 16 + (grp & 1) * 8 + lr;
                int sec = ks * 2 + (grp >> 1);
                uint32_t ad = aT + arow * 128 + ((sec ^ (arow & 7)) * 16);
                ldmx4(a[mi][0], a[mi][1], a[mi][2], a[mi][3], ad);
            }
            uint32_t b[8][2];
            #pragma unroll
            for (int nt = 0; nt < 4; ++nt) {
                int brow = wn * 64 + nt * 16 + (grp >> 1) * 8 + lr;
                int sec = ks * 2 + (grp & 1);
                uint32_t bd = bT + brow * 128 + ((sec ^ (brow & 7)) * 16);
                ldmx4(b[2 * nt][0], b[2 * nt][1], b[2 * nt + 1][0],
                      b[2 * nt + 1][1], bd);
            }
            #pragma unroll
            for (int mi = 0; mi < 2; ++mi)
                #pragma unroll
                for (int ni = 0; ni < 8; ++ni)
                    mma16816(acc[mi][ni], a[mi], b[ni]);
        }
        __syncthreads();
    }
    #undef STAGE

    // ---- epilogue: per-tile top-2 (values + BOTH indices), both dirs ------
    char* eb = dsmem;
    float* eRV1 = reinterpret_cast<float*>(eb);             // [2][128]
    float* eRV2 = reinterpret_cast<float*>(eb + 1024);
    int*   eRI1 = reinterpret_cast<int*>  (eb + 2048);
    int*   eRI2 = reinterpret_cast<int*>  (eb + 3072);
    float* eCV1 = reinterpret_cast<float*>(eb + 4096);      // [4][128]
    float* eCV2 = reinterpret_cast<float*>(eb + 6144);
    int*   eCI1 = reinterpret_cast<int*>  (eb + 8192);
    int*   eCI2 = reinterpret_cast<int*>  (eb + 10240);

    // rows (A->B)
    #pragma unroll
    for (int mi = 0; mi < 2; ++mi) {
        #pragma unroll
        for (int h = 0; h < 2; ++h) {
            int row = wm * 32 + mi * 16 + h * 8 + gq;
            float v1 = NEG_INF, v2 = NEG_INF; int i1 = 0, i2 = 0;
            #pragma unroll
            for (int ni = 0; ni < 8; ++ni)
                #pragma unroll
                for (int p2 = 0; p2 < 2; ++p2) {
                    float v = acc[mi][ni][h * 2 + p2];
                    int col = j0 + wn * 64 + ni * 8 + 2 * tq + p2;
                    if (v > v1) { v2 = v1; i2 = i1; v1 = v; i1 = col; }
                    else if (v > v2) { v2 = v; i2 = col; }
                }
            #pragma unroll
            for (int m = 1; m <= 2; m <<= 1) {
                float w1 = __shfl_xor_sync(0xffffffffu, v1, m);
                float w2 = __shfl_xor_sync(0xffffffffu, v2, m);
                int   j1 = __shfl_xor_sync(0xffffffffu, i1, m);
                int   j2 = __shfl_xor_sync(0xffffffffu, i2, m);
                merge22(v1, i1, v2, i2, w1, j1, w2, j2);
            }
            if (tq == 0) {
                eRV1[wn * 128 + row] = v1; eRV2[wn * 128 + row] = v2;
                eRI1[wn * 128 + row] = i1; eRI2[wn * 128 + row] = i2;
            }
        }
    }
    // cols (B->A)
    #pragma unroll
    for (int ni = 0; ni < 8; ++ni) {
        #pragma unroll
        for (int p2 = 0; p2 < 2; ++p2) {
            int colL = wn * 64 + ni * 8 + 2 * tq + p2;
            float v1 = NEG_INF, v2 = NEG_INF; int i1 = 0, i2 = 0;
            #pragma unroll
            for (int mi = 0; mi < 2; ++mi)
                #pragma unroll
                for (int h = 0; h < 2; ++h) {
                    float v = acc[mi][ni][h * 2 + p2];
                    int row = i0 + wm * 32 + mi * 16 + h * 8 + gq;
                    if (v > v1) { v2 = v1; i2 = i1; v1 = v; i1 = row; }
                    else if (v > v2) { v2 = v; i2 = row; }
                }
            #pragma unroll
            for (int m = 4; m <= 16; m <<= 1) {
                float w1 = __shfl_xor_sync(0xffffffffu, v1, m);
                float w2 = __shfl_xor_sync(0xffffffffu, v2, m);
                int   j1 = __shfl_xor_sync(0xffffffffu, i1, m);
                int   j2 = __shfl_xor_sync(0xffffffffu, i2, m);
                merge22(v1, i1, v2, i2, w1, j1, w2, j2);
            }
            if (gq == 0) {
                eCV1[wm * 128 + colL] = v1; eCV2[wm * 128 + colL] = v2;
                eCI1[wm * 128 + colL] = i1; eCI2[wm * 128 + colL] = i2;
            }
        }
    }
    __syncthreads();
    if (tid < 128) {
        float v1 = eRV1[tid], v2 = eRV2[tid]; int i1 = eRI1[tid], i2 = eRI2[tid];
        merge22(v1, i1, v2, i2, eRV1[128 + tid], eRI1[128 + tid],
                eRV2[128 + tid], eRI2[128 + tid]);
        size_t ro = (size_t)jT * N_DESC + i0 + tid;
        g_rowV1[ro] = v1; g_rowV2[ro] = v2; g_rowI1[ro] = i1; g_rowI2[ro] = i2;

        float c1 = eCV1[tid], c2 = eCV2[tid]; int ci1 = eCI1[tid], ci2 = eCI2[tid];
        #pragma unroll
        for (int g2 = 1; g2 < 4; ++g2)
            merge22(c1, ci1, c2, ci2, eCV1[g2 * 128 + tid], eCI1[g2 * 128 + tid],
                    eCV2[g2 * 128 + tid], eCI2[g2 * 128 + tid]);
        size_t co = (size_t)iT * N_DESC + j0 + tid;
        g_colV1[co] = c1; g_colV2[co] = c2; g_colI1[co] = ci1; g_colI2[co] = ci2;
    }
}

// ---- kernel 4: single-pass merge of 96 tile-partials -> 4 candidates ------
__global__ void cand_kernel() {
    int i = blockIdx.x * blockDim.x + threadIdx.x;
    if (i >= N_DESC) return;
    int dir = blockIdx.y;         // 0: rows, 1: cols
    const float* V1 = dir ? g_colV1 : g_rowV1;
    const float* V2 = dir ? g_colV2 : g_rowV2;
    const int*   I1 = dir ? g_colI1 : g_rowI1;
    const int*   I2 = dir ? g_colI2 : g_rowI2;
    float cv[NCAND]; int ci[NCAND];
    #pragma unroll
    for (int q = 0; q < NCAND; ++q) { cv[q] = NEG_INF; ci[q] = 0; }
    for (int s = 0; s < NT; ++s) {
        size_t o = (size_t)s * N_DESC + i;
        float w1 = V1[o], w2 = V2[o];
        int   j1 = I1[o], j2 = I2[o];
        #pragma unroll
        for (int e = 0; e < 2; ++e) {
            float v = e ? w2 : w1;
            int   ix = e ? j2 : j1;
            if (v > cv[NCAND - 1] || (v == cv[NCAND - 1] && ix < ci[NCAND - 1])) {
                cv[NCAND - 1] = v; ci[NCAND - 1] = ix;
                #pragma unroll
                for (int q = NCAND - 1; q > 0; --q)
                    if (cv[q] > cv[q - 1] ||
                        (cv[q] == cv[q - 1] && ci[q] < ci[q - 1])) {
                        float tv = cv[q]; cv[q] = cv[q - 1]; cv[q - 1] = tv;
                        int ti = ci[q]; ci[q] = ci[q - 1]; ci[q - 1] = ti;
                    }
            }
        }
    }
    #pragma unroll
    for (int q = 0; q < NCAND; ++q)
        g_cI[((size_t)dir * NCAND + q) * N_DESC + i] = ci[q];
}

// ---- kernel 5: fp32 rescore of NCAND candidates (one warp per row/col) ----
__global__ void rescore_kernel() {
    const int lane = threadIdx.x & 31;
    const int w = threadIdx.x >> 5;
    const int row = blockIdx.x * 8 + w;
    const int dir = blockIdx.y;
    if (row >= N_DESC) return;
    const float* X = dir ? g_fB : g_fA;
    const float* Y = dir ? g_fA : g_fB;
    int idx[NCAND];
    #pragma unroll
    for (int q = 0; q < NCAND; ++q)
        idx[q] = g_cI[((size_t)dir * NCAND + q) * N_DESC + row];
    float s[NCAND];
    #pragma unroll
    for (int q = 0; q < NCAND; ++q) s[q] = 0.f;
    const float4* xr = reinterpret_cast<const float4*>(X + (size_t)row * CH) + lane * 4;
    #pragma unroll
    for (int u = 0; u < 4; ++u) {
        float4 xa = xr[u];
        #pragma unroll
        for (int q = 0; q < NCAND; ++q) {
            float4 yb = *(reinterpret_cast<const float4*>(Y + (size_t)idx[q] * CH) +
                          lane * 4 + u);
            s[q] += xa.x * yb.x + xa.y * yb.y + xa.z * yb.z + xa.w * yb.w;
        }
    }
    #pragma unroll
    for (int m = 16; m > 0; m >>= 1)
        #pragma unroll
        for (int q = 0; q < NCAND; ++q)
            s[q] += __shfl_xor_sync(0xffffffffu, s[q], m);
    if (lane == 0) {
        float v1 = NEG_INF, v2 = NEG_INF; int i1 = 0;
        #pragma unroll
        for (int q = 0; q < NCAND; ++q) {
            if (s[q] > v1 || (s[q] == v1 && idx[q] < i1)) {
                v2 = v1; v1 = s[q]; i1 = idx[q];
            } else if (s[q] > v2) v2 = s[q];
        }
        if (dir == 0) { g_aV1[row] = v1; g_aV2[row] = v2; g_aI1[row] = i1; }
        else          { g_bV1[row] = v1; g_bV2[row] = v2; g_bI1[row] = i1; }
    }
}

// ---- kernel 6: mutual check + ratio test + output -------------------------
__global__ void match_kernel(float* __restrict__ out) {
    int i = blockIdx.x * blockDim.x + threadIdx.x;
    if (i >= N_DESC) return;
    float s1 = g_aV1[i], s2 = g_aV2[i];
    int   n12 = g_aI1[i];
    float r12 = (2.0f - 2.0f * s1) / (2.0f - 2.0f * s2 + EPS_T);
    int   n21 = g_bI1[n12];
    float r21 = (2.0f - 2.0f * g_bV1[n12]) / (2.0f - 2.0f * g_bV2[n12] + EPS_T);
    bool mask = (n21 == i) && (r12 <= RATIO_T) && (r21 <= RATIO_T);
    out[i]              = mask ? s1 : 0.0f;
    out[N_DESC + i]     = (float)n12;
    out[2 * N_DESC + i] = mask ? 1.0f : 0.0f;
}

// ---------------------------------------------------------------------------
extern "C" void kernel_launch(void* const* d_in, const int* in_sizes, int n_in,
                              void* d_out, int out_size) {
    const float* mA = (const float*)d_in[0];
    const float* mB = (const float*)d_in[1];
    float* out = (float*)d_out;

    cudaFuncSetAttribute(gemm_top2_kernel,
                         cudaFuncAttributeMaxDynamicSharedMemorySize, SMEM_GEMM);

    dim3 nb(N_DESC / 256, 2);
    norms_kernel<<<nb, 256>>>(mA, mB);

    dim3 pp(N_DESC / 64, CH / 64, 2);
    prep_kernel<<<pp, 256>>>(mA, mB);

    dim3 gb(NT, NT);
    gemm_top2_kernel<<<gb, 256, SMEM_GEMM>>>();

    dim3 cd(N_DESC / 256, 2);
    cand_kernel<<<cd, 256>>>();

    dim3 rs(N_DESC / 8, 2);
    rescore_kernel<<<rs, 256>>>();

    match_kernel<<<N_DESC / 256, 256>>>(out);
}

// round 12
// speedup vs baseline: 1.2604x; 1.0176x over previous
#include <cuda_runtime.h>
#include <cuda_bf16.h>
#include <cstdint>

// ---------------------------------------------------------------------------
// DeepFeatureMatcher: bf16 mma.sync screening GEMM (persistent CTAs, fused
// bidirectional per-tile top-2 with indices) -> two-stage parallel merge to
// 4 candidates per row/col -> exact fp32 rescore -> mutual + ratio test.
// Output (float32, 3*12288): [masked_sim | nn12 as float | mask as 0/1]
// ---------------------------------------------------------------------------

#define N_DESC 12288
#define CH     512
#define NT     96                    // 128-wide tiles per dim
#define NTILES (NT * NT)
#define NPERS  296                   // persistent CTAs (148 SMs x 2)
#define NCAND  4
#define RATIO_T 0.95f
#define EPS_T   1e-8f
#define SMEM_GEMM 65536              // 2 x (16KB A + 16KB B) double buffer
#define NEG_INF (-1e30f)

// ---- device global scratch (no allocation allowed) ------------------------
__device__ __align__(256) float         g_fA[N_DESC * CH];  // normalized fp32, desc-major
__device__ __align__(256) float         g_fB[N_DESC * CH];
__device__ __align__(256) __nv_bfloat16 g_bA[N_DESC * CH];  // normalized bf16, desc-major
__device__ __align__(256) __nv_bfloat16 g_bB[N_DESC * CH];
__device__ float g_rnA[N_DESC], g_rnB[N_DESC];
// per-tile top2 partials (both indices), rows: [jT][N], cols: [iT][N]
__device__ float g_rowV1[NT * N_DESC], g_rowV2[NT * N_DESC];
__device__ int   g_rowI1[NT * N_DESC], g_rowI2[NT * N_DESC];
__device__ float g_colV1[NT * N_DESC], g_colV2[NT * N_DESC];
__device__ int   g_colI1[NT * N_DESC], g_colI2[NT * N_DESC];
// level-1 merged (8 groups of 12 tiles), per dir
__device__ float g_l1V1[2 * 8 * N_DESC], g_l1V2[2 * 8 * N_DESC];
__device__ int   g_l1I1[2 * 8 * N_DESC], g_l1I2[2 * 8 * N_DESC];
// NCAND candidates per row/col, per dir
__device__ int   g_cI[2 * NCAND * N_DESC];
// rescored fp32 top-2
__device__ float g_aV1[N_DESC], g_aV2[N_DESC]; __device__ int g_aI1[N_DESC];
__device__ float g_bV1[N_DESC], g_bV2[N_DESC]; __device__ int g_bI1[N_DESC];

// ---- helpers --------------------------------------------------------------
__device__ __forceinline__ uint32_t smem_u32(const void* p) {
    uint32_t a;
    asm("{ .reg .u64 t; cvta.to.shared.u64 t, %1; cvt.u32.u64 %0, t; }"
        : "=r"(a) : "l"(p));
    return a;
}
__device__ __forceinline__ void ldmx4(uint32_t& r0, uint32_t& r1,
                                      uint32_t& r2, uint32_t& r3, uint32_t addr) {
    asm volatile("ldmatrix.sync.aligned.m8n8.x4.shared.b16 {%0,%1,%2,%3}, [%4];"
                 : "=r"(r0), "=r"(r1), "=r"(r2), "=r"(r3) : "r"(addr));
}
__device__ __forceinline__ void mma16816(float* c, const uint32_t* a,
                                         const uint32_t* b) {
    asm volatile(
        "mma.sync.aligned.m16n8k16.row.col.f32.bf16.bf16.f32 "
        "{%0,%1,%2,%3}, {%4,%5,%6,%7}, {%8,%9}, {%0,%1,%2,%3};"
        : "+f"(c[0]), "+f"(c[1]), "+f"(c[2]), "+f"(c[3])
        : "r"(a[0]), "r"(a[1]), "r"(a[2]), "r"(a[3]), "r"(b[0]), "r"(b[1]));
}
// merge top-2 list (w1,j1,w2,j2) into (v1,i1,v2,i2); lower index wins ties
__device__ __forceinline__ void merge22(float& v1, int& i1, float& v2, int& i2,
                                        float w1, int j1, float w2, int j2) {
    if (w1 > v1 || (w1 == v1 && j1 < i1)) {
        if (v1 > w2 || (v1 == w2 && i1 < j2)) { v2 = v1; i2 = i1; }
        else                                   { v2 = w2; i2 = j2; }
        v1 = w1; i1 = j1;
    } else if (w1 > v2 || (w1 == v2 && j1 < i2)) {
        v2 = w1; i2 = j1;
    }
}

// ---- kernel 1: inverse norms ----------------------------------------------
__global__ void norms_kernel(const float* __restrict__ mA,
                             const float* __restrict__ mB) {
    int i = blockIdx.x * blockDim.x + threadIdx.x;
    if (i >= N_DESC) return;
    const float* m = blockIdx.y ? mB : mA;
    float s = 0.f;
    #pragma unroll 8
    for (int c = 0; c < CH; ++c) {
        float v = m[(size_t)c * N_DESC + i];
        s = fmaf(v, v, s);
    }
    float r = 1.0f / sqrtf(s);
    if (blockIdx.y) g_rnB[i] = r; else g_rnA[i] = r;
}

// ---- kernel 2: normalize + transpose -> fp32 and bf16 desc-major ----------
__global__ void prep_kernel(const float* __restrict__ mA,
                            const float* __restrict__ mB) {
    __shared__ float t[64][65];
    const int tid = threadIdx.x;
    const int i0 = blockIdx.x * 64;
    const int c0 = blockIdx.y * 64;
    const float* m = blockIdx.z ? mB : mA;
    const float* rn = blockIdx.z ? g_rnB : g_rnA;
    float* gf = blockIdx.z ? g_fB : g_fA;
    __nv_bfloat16* gb = blockIdx.z ? g_bB : g_bA;

    const int ii = tid & 63, cb = tid >> 6;
    #pragma unroll
    for (int it = 0; it < 16; ++it) {
        int cc = it * 4 + cb;
        t[cc][ii] = m[(size_t)(c0 + cc) * N_DESC + i0 + ii] * rn[i0 + ii];
    }
    __syncthreads();

    const int cc2 = tid & 31, rw = tid >> 5;
    #pragma unroll
    for (int it = 0; it < 8; ++it) {
        int i = rw + it * 8;
        float v0 = t[2 * cc2][i], v1 = t[2 * cc2 + 1][i];
        size_t base = (size_t)(i0 + i) * CH + c0 + 2 * cc2;
        *reinterpret_cast<float2*>(&gf[base]) = make_float2(v0, v1);
        uint32_t pk = ((uint32_t)__bfloat16_as_ushort(__float2bfloat16_rn(v1)) << 16) |
                      (uint32_t)__bfloat16_as_ushort(__float2bfloat16_rn(v0));
        *reinterpret_cast<uint32_t*>(&gb[base]) = pk;
    }
}

// ---- kernel 3: persistent bf16 screening GEMM + per-tile top-2 ------------
extern __shared__ char dsmem[];
__global__ __launch_bounds__(256, 2) void gemm_top2_kernel() {
    const int tid = threadIdx.x;
    const int wid = tid >> 5, lane = tid & 31;
    const int wm = wid >> 1, wn = wid & 1;     // warp tile: 32 rows x 64 cols
    const int grp = lane >> 3, lr = lane & 7;
    const int gq = lane >> 2, tq = lane & 3;
    const uint32_t sb = smem_u32(dsmem);

    const int r0 = tid >> 3;       // staging row 0..31
    const int c8 = tid & 7;        // 16B sector

    // epilogue scratch aliases (overlap stage buffer 0; guarded by syncthreads)
    char* eb = dsmem;
    float* eRV1 = reinterpret_cast<float*>(eb);             // [2][128]
    float* eRV2 = reinterpret_cast<float*>(eb + 1024);
    int*   eRI1 = reinterpret_cast<int*>  (eb + 2048);
    int*   eRI2 = reinterpret_cast<int*>  (eb + 3072);
    float* eCV1 = reinterpret_cast<float*>(eb + 4096);      // [4][128]
    float* eCV2 = reinterpret_cast<float*>(eb + 6144);
    int*   eCI1 = reinterpret_cast<int*>  (eb + 8192);
    int*   eCI2 = reinterpret_cast<int*>  (eb + 10240);

    for (int t = blockIdx.x; t < NTILES; t += NPERS) {
        const int iT = t / NT, jT = t - iT * NT;
        const int i0 = iT * 128, j0 = jT * 128;

        __syncthreads();   // previous tile's epilogue smem reads done

        float acc[2][8][4];
        #pragma unroll
        for (int mi = 0; mi < 2; ++mi)
            #pragma unroll
            for (int ni = 0; ni < 8; ++ni)
                #pragma unroll
                for (int c = 0; c < 4; ++c) acc[mi][ni][c] = 0.f;

        // ---- cp.async staging of one (A,B) 128x64 bf16 chunk pair ---------
        #define STAGE(buf, chn) do {                                           \
            const size_t kof = (size_t)(chn) * 64;                             \
            _Pragma("unroll")                                                  \
            for (int it = 0; it < 4; ++it) {                                   \
                int r = r0 + it * 32;                                          \
                uint32_t off = (uint32_t)r * 128 + c8 * 16;                    \
                uint32_t sw = off ^ ((off >> 3) & 0x70);                       \
                const __nv_bfloat16* ga = g_bA + (size_t)(i0 + r) * CH + kof + c8 * 8; \
                uint32_t da = sb + (buf) * 32768 + sw;                         \
                asm volatile("cp.async.cg.shared.global [%0], [%1], 16;"       \
                             :: "r"(da), "l"(ga) : "memory");                  \
                const __nv_bfloat16* gbp = g_bB + (size_t)(j0 + r) * CH + kof + c8 * 8; \
                uint32_t db = sb + (buf) * 32768 + 16384 + sw;                 \
                asm volatile("cp.async.cg.shared.global [%0], [%1], 16;"       \
                             :: "r"(db), "l"(gbp) : "memory");                 \
            }                                                                  \
            asm volatile("cp.async.commit_group;" ::: "memory");               \
        } while (0)

        STAGE(0, 0);
        for (int ch = 0; ch < 8; ++ch) {
            if (ch + 1 < 8) {
                STAGE((ch + 1) & 1, ch + 1);
                asm volatile("cp.async.wait_group 1;" ::: "memory");
            } else {
                asm volatile("cp.async.wait_group 0;" ::: "memory");
            }
            __syncthreads();

            const uint32_t aT = sb + (ch & 1) * 32768;
            const uint32_t bT = aT + 16384;
            #pragma unroll
            for (int ks = 0; ks < 4; ++ks) {
                uint32_t a[2][4];
                #pragma unroll
                for (int mi = 0; mi < 2; ++mi) {
                    int arow = wm * 32 + mi * 16 + (grp & 1) * 8 + lr;
                    int sec = ks * 2 + (grp >> 1);
                    uint32_t ad = aT + arow * 128 + ((sec ^ (arow & 7)) * 16);
                    ldmx4(a[mi][0], a[mi][1], a[mi][2], a[mi][3], ad);
                }
                uint32_t b[8][2];
                #pragma unroll
                for (int nt = 0; nt < 4; ++nt) {
                    int brow = wn * 64 + nt * 16 + (grp >> 1) * 8 + lr;
                    int sec = ks * 2 + (grp & 1);
                    uint32_t bd = bT + brow * 128 + ((sec ^ (brow & 7)) * 16);
                    ldmx4(b[2 * nt][0], b[2 * nt][1], b[2 * nt + 1][0],
                          b[2 * nt + 1][1], bd);
                }
                #pragma unroll
                for (int mi = 0; mi < 2; ++mi)
                    #pragma unroll
                    for (int ni = 0; ni < 8; ++ni)
                        mma16816(acc[mi][ni], a[mi], b[ni]);
            }
            __syncthreads();
        }
        #undef STAGE

        // ---- epilogue: per-tile top-2 (values + BOTH indices), both dirs --
        // rows (A->B)
        #pragma unroll
        for (int mi = 0; mi < 2; ++mi) {
            #pragma unroll
            for (int h = 0; h < 2; ++h) {
                int row = wm * 32 + mi * 16 + h * 8 + gq;
                float v1 = NEG_INF, v2 = NEG_INF; int i1 = 0, i2 = 0;
                #pragma unroll
                for (int ni = 0; ni < 8; ++ni)
                    #pragma unroll
                    for (int p2 = 0; p2 < 2; ++p2) {
                        float v = acc[mi][ni][h * 2 + p2];
                        int col = j0 + wn * 64 + ni * 8 + 2 * tq + p2;
                        if (v > v1) { v2 = v1; i2 = i1; v1 = v; i1 = col; }
                        else if (v > v2) { v2 = v; i2 = col; }
                    }
                #pragma unroll
                for (int m = 1; m <= 2; m <<= 1) {
                    float w1 = __shfl_xor_sync(0xffffffffu, v1, m);
                    float w2 = __shfl_xor_sync(0xffffffffu, v2, m);
                    int   j1 = __shfl_xor_sync(0xffffffffu, i1, m);
                    int   j2 = __shfl_xor_sync(0xffffffffu, i2, m);
                    merge22(v1, i1, v2, i2, w1, j1, w2, j2);
                }
                if (tq == 0) {
                    eRV1[wn * 128 + row] = v1; eRV2[wn * 128 + row] = v2;
                    eRI1[wn * 128 + row] = i1; eRI2[wn * 128 + row] = i2;
                }
            }
        }
        // cols (B->A)
        #pragma unroll
        for (int ni = 0; ni < 8; ++ni) {
            #pragma unroll
            for (int p2 = 0; p2 < 2; ++p2) {
                int colL = wn * 64 + ni * 8 + 2 * tq + p2;
                float v1 = NEG_INF, v2 = NEG_INF; int i1 = 0, i2 = 0;
                #pragma unroll
                for (int mi = 0; mi < 2; ++mi)
                    #pragma unroll
                    for (int h = 0; h < 2; ++h) {
                        float v = acc[mi][ni][h * 2 + p2];
                        int row = i0 + wm * 32 + mi * 16 + h * 8 + gq;
                        if (v > v1) { v2 = v1; i2 = i1; v1 = v; i1 = row; }
                        else if (v > v2) { v2 = v; i2 = row; }
                    }
                #pragma unroll
                for (int m = 4; m <= 16; m <<= 1) {
                    float w1 = __shfl_xor_sync(0xffffffffu, v1, m);
                    float w2 = __shfl_xor_sync(0xffffffffu, v2, m);
                    int   j1 = __shfl_xor_sync(0xffffffffu, i1, m);
                    int   j2 = __shfl_xor_sync(0xffffffffu, i2, m);
                    merge22(v1, i1, v2, i2, w1, j1, w2, j2);
                }
                if (gq == 0) {
                    eCV1[wm * 128 + colL] = v1; eCV2[wm * 128 + colL] = v2;
                    eCI1[wm * 128 + colL] = i1; eCI2[wm * 128 + colL] = i2;
                }
            }
        }
        __syncthreads();
        if (tid < 128) {
            float v1 = eRV1[tid], v2 = eRV2[tid]; int i1 = eRI1[tid], i2 = eRI2[tid];
            merge22(v1, i1, v2, i2, eRV1[128 + tid], eRI1[128 + tid],
                    eRV2[128 + tid], eRI2[128 + tid]);
            size_t ro = (size_t)jT * N_DESC + i0 + tid;
            g_rowV1[ro] = v1; g_rowV2[ro] = v2; g_rowI1[ro] = i1; g_rowI2[ro] = i2;

            float c1 = eCV1[tid], c2 = eCV2[tid]; int ci1 = eCI1[tid], ci2 = eCI2[tid];
            #pragma unroll
            for (int g2 = 1; g2 < 4; ++g2)
                merge22(c1, ci1, c2, ci2, eCV1[g2 * 128 + tid], eCI1[g2 * 128 + tid],
                        eCV2[g2 * 128 + tid], eCI2[g2 * 128 + tid]);
            size_t co = (size_t)iT * N_DESC + j0 + tid;
            g_colV1[co] = c1; g_colV2[co] = c2; g_colI1[co] = ci1; g_colI2[co] = ci2;
        }
    }
}

// ---- kernel 4: level-1 merge (12 tiles per group, 8 groups, both dirs) ----
__global__ void reduce1_kernel() {
    int i = blockIdx.x * blockDim.x + threadIdx.x;
    if (i >= N_DESC) return;
    int g = blockIdx.y;           // 0..7
    int dir = blockIdx.z;         // 0: rows, 1: cols
    const float* V1 = dir ? g_colV1 : g_rowV1;
    const float* V2 = dir ? g_colV2 : g_rowV2;
    const int*   I1 = dir ? g_colI1 : g_rowI1;
    const int*   I2 = dir ? g_colI2 : g_rowI2;
    float v1 = NEG_INF, v2 = NEG_INF; int i1 = 0, i2 = 0;
    for (int t = 0; t < 12; ++t) {
        size_t o = (size_t)(g * 12 + t) * N_DESC + i;
        merge22(v1, i1, v2, i2, V1[o], I1[o], V2[o], I2[o]);
    }
    size_t o = (size_t)(dir * 8 + g) * N_DESC + i;
    g_l1V1[o] = v1; g_l1V2[o] = v2; g_l1I1[o] = i1; g_l1I2[o] = i2;
}

// ---- kernel 5: merge 8 groups -> NCAND candidates per row/col -------------
__global__ void cand_kernel() {
    int i = blockIdx.x * blockDim.x + threadIdx.x;
    if (i >= N_DESC) return;
    int dir = blockIdx.y;
    float cv[NCAND]; int ci[NCAND];
    #pragma unroll
    for (int q = 0; q < NCAND; ++q) { cv[q] = NEG_INF; ci[q] = 0; }
    for (int g = 0; g < 8; ++g) {
        size_t o = (size_t)(dir * 8 + g) * N_DESC + i;
        #pragma unroll
        for (int e = 0; e < 2; ++e) {
            float v = e ? g_l1V2[o] : g_l1V1[o];
            int   ix = e ? g_l1I2[o] : g_l1I1[o];
            if (v > cv[NCAND - 1] || (v == cv[NCAND - 1] && ix < ci[NCAND - 1])) {
                cv[NCAND - 1] = v; ci[NCAND - 1] = ix;
                #pragma unroll
                for (int q = NCAND - 1; q > 0; --q)
                    if (cv[q] > cv[q - 1] ||
                        (cv[q] == cv[q - 1] && ci[q] < ci[q - 1])) {
                        float tv = cv[q]; cv[q] = cv[q - 1]; cv[q - 1] = tv;
                        int ti = ci[q]; ci[q] = ci[q - 1]; ci[q - 1] = ti;
                    }
            }
        }
    }
    #pragma unroll
    for (int q = 0; q < NCAND; ++q)
        g_cI[((size_t)dir * NCAND + q) * N_DESC + i] = ci[q];
}

// ---- kernel 6: fp32 rescore of NCAND candidates (one warp per row/col) ----
__global__ void rescore_kernel() {
    const int lane = threadIdx.x & 31;
    const int w = threadIdx.x >> 5;
    const int row = blockIdx.x * 8 + w;
    const int dir = blockIdx.y;
    if (row >= N_DESC) return;
    const float* X = dir ? g_fB : g_fA;
    const float* Y = dir ? g_fA : g_fB;
    int idx[NCAND];
    #pragma unroll
    for (int q = 0; q < NCAND; ++q)
        idx[q] = g_cI[((size_t)dir * NCAND + q) * N_DESC + row];
    float s[NCAND];
    #pragma unroll
    for (int q = 0; q < NCAND; ++q) s[q] = 0.f;
    const float4* xr = reinterpret_cast<const float4*>(X + (size_t)row * CH) + lane * 4;
    #pragma unroll
    for (int u = 0; u < 4; ++u) {
        float4 xa = xr[u];
        #pragma unroll
        for (int q = 0; q < NCAND; ++q) {
            float4 yb = *(reinterpret_cast<const float4*>(Y + (size_t)idx[q] * CH) +
                          lane * 4 + u);
            s[q] += xa.x * yb.x + xa.y * yb.y + xa.z * yb.z + xa.w * yb.w;
        }
    }
    #pragma unroll
    for (int m = 16; m > 0; m >>= 1)
        #pragma unroll
        for (int q = 0; q < NCAND; ++q)
            s[q] += __shfl_xor_sync(0xffffffffu, s[q], m);
    if (lane == 0) {
        float v1 = NEG_INF, v2 = NEG_INF; int i1 = 0;
        #pragma unroll
        for (int q = 0; q < NCAND; ++q) {
            if (s[q] > v1 || (s[q] == v1 && idx[q] < i1)) {
                v2 = v1; v1 = s[q]; i1 = idx[q];
            } else if (s[q] > v2) v2 = s[q];
        }
        if (dir == 0) { g_aV1[row] = v1; g_aV2[row] = v2; g_aI1[row] = i1; }
        else          { g_bV1[row] = v1; g_bV2[row] = v2; g_bI1[row] = i1; }
    }
}

// ---- kernel 7: mutual check + ratio test + output -------------------------
__global__ void match_kernel(float* __restrict__ out) {
    int i = blockIdx.x * blockDim.x + threadIdx.x;
    if (i >= N_DESC) return;
    float s1 = g_aV1[i], s2 = g_aV2[i];
    int   n12 = g_aI1[i];
    float r12 = (2.0f - 2.0f * s1) / (2.0f - 2.0f * s2 + EPS_T);
    int   n21 = g_bI1[n12];
    float r21 = (2.0f - 2.0f * g_bV1[n12]) / (2.0f - 2.0f * g_bV2[n12] + EPS_T);
    bool mask = (n21 == i) && (r12 <= RATIO_T) && (r21 <= RATIO_T);
    out[i]              = mask ? s1 : 0.0f;
    out[N_DESC + i]     = (float)n12;
    out[2 * N_DESC + i] = mask ? 1.0f : 0.0f;
}

// ---------------------------------------------------------------------------
extern "C" void kernel_launch(void* const* d_in, const int* in_sizes, int n_in,
                              void* d_out, int out_size) {
    const float* mA = (const float*)d_in[0];
    const float* mB = (const float*)d_in[1];
    float* out = (float*)d_out;

    cudaFuncSetAttribute(gemm_top2_kernel,
                         cudaFuncAttributeMaxDynamicSharedMemorySize, SMEM_GEMM);

    dim3 nb(N_DESC / 256, 2);
    norms_kernel<<<nb, 256>>>(mA, mB);

    dim3 pp(N_DESC / 64, CH / 64, 2);
    prep_kernel<<<pp, 256>>>(mA, mB);

    gemm_top2_kernel<<<NPERS, 256, SMEM_GEMM>>>();

    dim3 r1(N_DESC / 256, 8, 2);
    reduce1_kernel<<<r1, 256>>>();

    dim3 cd(N_DESC / 256, 2);
    cand_kernel<<<cd, 256>>>();

    dim3 rs(N_DESC / 8, 2);
    rescore_kernel<<<rs, 256>>>();

    match_kernel<<<N_DESC / 256, 256>>>(out);
}

// round 13
// speedup vs baseline: 1.3271x; 1.0529x over previous
#include <cuda_runtime.h>
#include <cuda_bf16.h>
#include <cstdint>

// ---------------------------------------------------------------------------
// DeepFeatureMatcher: bf16 mma.sync screening GEMM (fused bidirectional
// per-tile top-2 with indices) -> two-stage parallel merge to 4 candidates
// (values + indices) -> gap-gated fp32 rescore (fast path skips memory
// traffic when screened gap is decisive) -> mutual + ratio test.
// Output (float32, 3*12288): [masked_sim | nn12 as float | mask as 0/1]
// ---------------------------------------------------------------------------

#define N_DESC 12288
#define CH     512
#define NT     96                    // 128-wide tiles per dim
#define NCAND  4
#define RATIO_T 0.95f
#define EPS_T   1e-8f
#define SMEM_GEMM 65536              // 2 x (16KB A + 16KB B) double buffer
#define NEG_INF (-1e30f)
#define GAP_T  1e-3f                 // ~14 sigma of bf16 screening noise

// ---- device global scratch (no allocation allowed) ------------------------
__device__ __align__(256) float         g_fA[N_DESC * CH];  // normalized fp32, desc-major
__device__ __align__(256) float         g_fB[N_DESC * CH];
__device__ __align__(256) __nv_bfloat16 g_bA[N_DESC * CH];  // normalized bf16, desc-major
__device__ __align__(256) __nv_bfloat16 g_bB[N_DESC * CH];
__device__ float g_rnA[N_DESC], g_rnB[N_DESC];
// per-tile top2 partials (both indices), rows: [jT][N], cols: [iT][N]
__device__ float g_rowV1[NT * N_DESC], g_rowV2[NT * N_DESC];
__device__ int   g_rowI1[NT * N_DESC], g_rowI2[NT * N_DESC];
__device__ float g_colV1[NT * N_DESC], g_colV2[NT * N_DESC];
__device__ int   g_colI1[NT * N_DESC], g_colI2[NT * N_DESC];
// level-1 merged (8 groups of 12 tiles), per dir
__device__ float g_l1V1[2 * 8 * N_DESC], g_l1V2[2 * 8 * N_DESC];
__device__ int   g_l1I1[2 * 8 * N_DESC], g_l1I2[2 * 8 * N_DESC];
// NCAND candidates per row/col, per dir (indices AND screened values)
__device__ int   g_cI[2 * NCAND * N_DESC];
__device__ float g_cV[2 * NCAND * N_DESC];
// rescored fp32 top-2
__device__ float g_aV1[N_DESC], g_aV2[N_DESC]; __device__ int g_aI1[N_DESC];
__device__ float g_bV1[N_DESC], g_bV2[N_DESC]; __device__ int g_bI1[N_DESC];

// ---- helpers --------------------------------------------------------------
__device__ __forceinline__ uint32_t smem_u32(const void* p) {
    uint32_t a;
    asm("{ .reg .u64 t; cvta.to.shared.u64 t, %1; cvt.u32.u64 %0, t; }"
        : "=r"(a) : "l"(p));
    return a;
}
__device__ __forceinline__ void ldmx4(uint32_t& r0, uint32_t& r1,
                                      uint32_t& r2, uint32_t& r3, uint32_t addr) {
    asm volatile("ldmatrix.sync.aligned.m8n8.x4.shared.b16 {%0,%1,%2,%3}, [%4];"
                 : "=r"(r0), "=r"(r1), "=r"(r2), "=r"(r3) : "r"(addr));
}
__device__ __forceinline__ void mma16816(float* c, const uint32_t* a,
                                         const uint32_t* b) {
    asm volatile(
        "mma.sync.aligned.m16n8k16.row.col.f32.bf16.bf16.f32 "
        "{%0,%1,%2,%3}, {%4,%5,%6,%7}, {%8,%9}, {%0,%1,%2,%3};"
        : "+f"(c[0]), "+f"(c[1]), "+f"(c[2]), "+f"(c[3])
        : "r"(a[0]), "r"(a[1]), "r"(a[2]), "r"(a[3]), "r"(b[0]), "r"(b[1]));
}
// merge top-2 list (w1,j1,w2,j2) into (v1,i1,v2,i2); lower index wins ties
__device__ __forceinline__ void merge22(float& v1, int& i1, float& v2, int& i2,
                                        float w1, int j1, float w2, int j2) {
    if (w1 > v1 || (w1 == v1 && j1 < i1)) {
        if (v1 > w2 || (v1 == w2 && i1 < j2)) { v2 = v1; i2 = i1; }
        else                                   { v2 = w2; i2 = j2; }
        v1 = w1; i1 = j1;
    } else if (w1 > v2 || (w1 == v2 && j1 < i2)) {
        v2 = w1; i2 = j1;
    }
}

// ---- kernel 1: inverse norms ----------------------------------------------
__global__ void norms_kernel(const float* __restrict__ mA,
                             const float* __restrict__ mB) {
    int i = blockIdx.x * blockDim.x + threadIdx.x;
    if (i >= N_DESC) return;
    const float* m = blockIdx.y ? mB : mA;
    float s = 0.f;
    #pragma unroll 8
    for (int c = 0; c < CH; ++c) {
        float v = m[(size_t)c * N_DESC + i];
        s = fmaf(v, v, s);
    }
    float r = 1.0f / sqrtf(s);
    if (blockIdx.y) g_rnB[i] = r; else g_rnA[i] = r;
}

// ---- kernel 2: normalize + transpose -> fp32 and bf16 desc-major ----------
__global__ void prep_kernel(const float* __restrict__ mA,
                            const float* __restrict__ mB) {
    __shared__ float t[64][65];
    const int tid = threadIdx.x;
    const int i0 = blockIdx.x * 64;
    const int c0 = blockIdx.y * 64;
    const float* m = blockIdx.z ? mB : mA;
    const float* rn = blockIdx.z ? g_rnB : g_rnA;
    float* gf = blockIdx.z ? g_fB : g_fA;
    __nv_bfloat16* gb = blockIdx.z ? g_bB : g_bA;

    const int ii = tid & 63, cb = tid >> 6;
    #pragma unroll
    for (int it = 0; it < 16; ++it) {
        int cc = it * 4 + cb;
        t[cc][ii] = m[(size_t)(c0 + cc) * N_DESC + i0 + ii] * rn[i0 + ii];
    }
    __syncthreads();

    const int cc2 = tid & 31, rw = tid >> 5;
    #pragma unroll
    for (int it = 0; it < 8; ++it) {
        int i = rw + it * 8;
        float v0 = t[2 * cc2][i], v1 = t[2 * cc2 + 1][i];
        size_t base = (size_t)(i0 + i) * CH + c0 + 2 * cc2;
        *reinterpret_cast<float2*>(&gf[base]) = make_float2(v0, v1);
        uint32_t pk = ((uint32_t)__bfloat16_as_ushort(__float2bfloat16_rn(v1)) << 16) |
                      (uint32_t)__bfloat16_as_ushort(__float2bfloat16_rn(v0));
        *reinterpret_cast<uint32_t*>(&gb[base]) = pk;
    }
}

// ---- kernel 3: bf16 screening GEMM + per-tile bidirectional top-2 ---------
extern __shared__ char dsmem[];
__global__ __launch_bounds__(256, 2) void gemm_top2_kernel() {
    const int tid = threadIdx.x;
    const int wid = tid >> 5, lane = tid & 31;
    const int wm = wid >> 1, wn = wid & 1;     // warp tile: 32 rows x 64 cols
    const int grp = lane >> 3, lr = lane & 7;
    const int gq = lane >> 2, tq = lane & 3;
    const int iT = blockIdx.x, jT = blockIdx.y;
    const int i0 = iT * 128, j0 = jT * 128;
    const uint32_t sb = smem_u32(dsmem);

    float acc[2][8][4];
    #pragma unroll
    for (int mi = 0; mi < 2; ++mi)
        #pragma unroll
        for (int ni = 0; ni < 8; ++ni)
            #pragma unroll
            for (int c = 0; c < 4; ++c) acc[mi][ni][c] = 0.f;

    const int r0 = tid >> 3;       // staging row 0..31
    const int c8 = tid & 7;        // 16B sector

    // ---- cp.async staging of one (A,B) 128x64 bf16 chunk pair -------------
    #define STAGE(buf, chn) do {                                               \
        const size_t kof = (size_t)(chn) * 64;                                 \
        _Pragma("unroll")                                                      \
        for (int it = 0; it < 4; ++it) {                                       \
            int r = r0 + it * 32;                                              \
            uint32_t off = (uint32_t)r * 128 + c8 * 16;                        \
            uint32_t sw = off ^ ((off >> 3) & 0x70);                           \
            const __nv_bfloat16* ga = g_bA + (size_t)(i0 + r) * CH + kof + c8 * 8; \
            uint32_t da = sb + (buf) * 32768 + sw;                             \
            asm volatile("cp.async.cg.shared.global [%0], [%1], 16;"           \
                         :: "r"(da), "l"(ga) : "memory");                      \
            const __nv_bfloat16* gbp = g_bB + (size_t)(j0 + r) * CH + kof + c8 * 8; \
            uint32_t db = sb + (buf) * 32768 + 16384 + sw;                     \
            asm volatile("cp.async.cg.shared.global [%0], [%1], 16;"           \
                         :: "r"(db), "l"(gbp) : "memory");                     \
        }                                                                      \
        asm volatile("cp.async.commit_group;" ::: "memory");                   \
    } while (0)

    STAGE(0, 0);
    for (int ch = 0; ch < 8; ++ch) {
        if (ch + 1 < 8) {
            STAGE((ch + 1) & 1, ch + 1);
            asm volatile("cp.async.wait_group 1;" ::: "memory");
        } else {
            asm volatile("cp.async.wait_group 0;" ::: "memory");
        }
        __syncthreads();

        const uint32_t aT = sb + (ch & 1) * 32768;
        const uint32_t bT = aT + 16384;
        #pragma unroll
        for (int ks = 0; ks < 4; ++ks) {
            uint32_t a[2][4];
            #pragma unroll
            for (int mi = 0; mi < 2; ++mi) {
                int arow = wm * 32 + mi * 16 + (grp & 1) * 8 + lr;
                int sec = ks * 2 + (grp >> 1);
                uint32_t ad = aT + arow * 128 + ((sec ^ (arow & 7)) * 16);
                ldmx4(a[mi][0], a[mi][1], a[mi][2], a[mi][3], ad);
            }
            uint32_t b[8][2];
            #pragma unroll
            for (int nt = 0; nt < 4; ++nt) {
                int brow = wn * 64 + nt * 16 + (grp >> 1) * 8 + lr;
                int sec = ks * 2 + (grp & 1);
                uint32_t bd = bT + brow * 128 + ((sec ^ (brow & 7)) * 16);
                ldmx4(b[2 * nt][0], b[2 * nt][1], b[2 * nt + 1][0],
                      b[2 * nt + 1][1], bd);
            }
            #pragma unroll
            for (int mi = 0; mi < 2; ++mi)
                #pragma unroll
                for (int ni = 0; ni < 8; ++ni)
                    mma16816(acc[mi][ni], a[mi], b[ni]);
        }
        __syncthreads();
    }
    #undef STAGE

    // ---- epilogue: per-tile top-2 (values + BOTH indices), both dirs ------
    char* eb = dsmem;
    float* eRV1 = reinterpret_cast<float*>(eb);             // [2][128]
    float* eRV2 = reinterpret_cast<float*>(eb + 1024);
    int*   eRI1 = reinterpret_cast<int*>  (eb + 2048);
    int*   eRI2 = reinterpret_cast<int*>  (eb + 3072);
    float* eCV1 = reinterpret_cast<float*>(eb + 4096);      // [4][128]
    float* eCV2 = reinterpret_cast<float*>(eb + 6144);
    int*   eCI1 = reinterpret_cast<int*>  (eb + 8192);
    int*   eCI2 = reinterpret_cast<int*>  (eb + 10240);

    // rows (A->B)
    #pragma unroll
    for (int mi = 0; mi < 2; ++mi) {
        #pragma unroll
        for (int h = 0; h < 2; ++h) {
            int row = wm * 32 + mi * 16 + h * 8 + gq;
            float v1 = NEG_INF, v2 = NEG_INF; int i1 = 0, i2 = 0;
            #pragma unroll
            for (int ni = 0; ni < 8; ++ni)
                #pragma unroll
                for (int p2 = 0; p2 < 2; ++p2) {
                    float v = acc[mi][ni][h * 2 + p2];
                    int col = j0 + wn * 64 + ni * 8 + 2 * tq + p2;
                    if (v > v1) { v2 = v1; i2 = i1; v1 = v; i1 = col; }
                    else if (v > v2) { v2 = v; i2 = col; }
                }
            #pragma unroll
            for (int m = 1; m <= 2; m <<= 1) {
                float w1 = __shfl_xor_sync(0xffffffffu, v1, m);
                float w2 = __shfl_xor_sync(0xffffffffu, v2, m);
                int   j1 = __shfl_xor_sync(0xffffffffu, i1, m);
                int   j2 = __shfl_xor_sync(0xffffffffu, i2, m);
                merge22(v1, i1, v2, i2, w1, j1, w2, j2);
            }
            if (tq == 0) {
                eRV1[wn * 128 + row] = v1; eRV2[wn * 128 + row] = v2;
                eRI1[wn * 128 + row] = i1; eRI2[wn * 128 + row] = i2;
            }
        }
    }
    // cols (B->A)
    #pragma unroll
    for (int ni = 0; ni < 8; ++ni) {
        #pragma unroll
        for (int p2 = 0; p2 < 2; ++p2) {
            int colL = wn * 64 + ni * 8 + 2 * tq + p2;
            float v1 = NEG_INF, v2 = NEG_INF; int i1 = 0, i2 = 0;
            #pragma unroll
            for (int mi = 0; mi < 2; ++mi)
                #pragma unroll
                for (int h = 0; h < 2; ++h) {
                    float v = acc[mi][ni][h * 2 + p2];
                    int row = i0 + wm * 32 + mi * 16 + h * 8 + gq;
                    if (v > v1) { v2 = v1; i2 = i1; v1 = v; i1 = row; }
                    else if (v > v2) { v2 = v; i2 = row; }
                }
            #pragma unroll
            for (int m = 4; m <= 16; m <<= 1) {
                float w1 = __shfl_xor_sync(0xffffffffu, v1, m);
                float w2 = __shfl_xor_sync(0xffffffffu, v2, m);
                int   j1 = __shfl_xor_sync(0xffffffffu, i1, m);
                int   j2 = __shfl_xor_sync(0xffffffffu, i2, m);
                merge22(v1, i1, v2, i2, w1, j1, w2, j2);
            }
            if (gq == 0) {
                eCV1[wm * 128 + colL] = v1; eCV2[wm * 128 + colL] = v2;
                eCI1[wm * 128 + colL] = i1; eCI2[wm * 128 + colL] = i2;
            }
        }
    }
    __syncthreads();
    if (tid < 128) {
        float v1 = eRV1[tid], v2 = eRV2[tid]; int i1 = eRI1[tid], i2 = eRI2[tid];
        merge22(v1, i1, v2, i2, eRV1[128 + tid], eRI1[128 + tid],
                eRV2[128 + tid], eRI2[128 + tid]);
        size_t ro = (size_t)jT * N_DESC + i0 + tid;
        g_rowV1[ro] = v1; g_rowV2[ro] = v2; g_rowI1[ro] = i1; g_rowI2[ro] = i2;

        float c1 = eCV1[tid], c2 = eCV2[tid]; int ci1 = eCI1[tid], ci2 = eCI2[tid];
        #pragma unroll
        for (int g2 = 1; g2 < 4; ++g2)
            merge22(c1, ci1, c2, ci2, eCV1[g2 * 128 + tid], eCI1[g2 * 128 + tid],
                    eCV2[g2 * 128 + tid], eCI2[g2 * 128 + tid]);
        size_t co = (size_t)iT * N_DESC + j0 + tid;
        g_colV1[co] = c1; g_colV2[co] = c2; g_colI1[co] = ci1; g_colI2[co] = ci2;
    }
}

// ---- kernel 4: level-1 merge (12 tiles per group, 8 groups, both dirs) ----
__global__ void reduce1_kernel() {
    int i = blockIdx.x * blockDim.x + threadIdx.x;
    if (i >= N_DESC) return;
    int g = blockIdx.y;           // 0..7
    int dir = blockIdx.z;         // 0: rows, 1: cols
    const float* V1 = dir ? g_colV1 : g_rowV1;
    const float* V2 = dir ? g_colV2 : g_rowV2;
    const int*   I1 = dir ? g_colI1 : g_rowI1;
    const int*   I2 = dir ? g_colI2 : g_rowI2;
    float v1 = NEG_INF, v2 = NEG_INF; int i1 = 0, i2 = 0;
    for (int t = 0; t < 12; ++t) {
        size_t o = (size_t)(g * 12 + t) * N_DESC + i;
        merge22(v1, i1, v2, i2, V1[o], I1[o], V2[o], I2[o]);
    }
    size_t o = (size_t)(dir * 8 + g) * N_DESC + i;
    g_l1V1[o] = v1; g_l1V2[o] = v2; g_l1I1[o] = i1; g_l1I2[o] = i2;
}

// ---- kernel 5: merge 8 groups -> NCAND candidates (values + indices) ------
__global__ void cand_kernel() {
    int i = blockIdx.x * blockDim.x + threadIdx.x;
    if (i >= N_DESC) return;
    int dir = blockIdx.y;
    float cv[NCAND]; int ci[NCAND];
    #pragma unroll
    for (int q = 0; q < NCAND; ++q) { cv[q] = NEG_INF; ci[q] = 0; }
    for (int g = 0; g < 8; ++g) {
        size_t o = (size_t)(dir * 8 + g) * N_DESC + i;
        #pragma unroll
        for (int e = 0; e < 2; ++e) {
            float v = e ? g_l1V2[o] : g_l1V1[o];
            int   ix = e ? g_l1I2[o] : g_l1I1[o];
            if (v > cv[NCAND - 1] || (v == cv[NCAND - 1] && ix < ci[NCAND - 1])) {
                cv[NCAND - 1] = v; ci[NCAND - 1] = ix;
                #pragma unroll
                for (int q = NCAND - 1; q > 0; --q)
                    if (cv[q] > cv[q - 1] ||
                        (cv[q] == cv[q - 1] && ci[q] < ci[q - 1])) {
                        float tv = cv[q]; cv[q] = cv[q - 1]; cv[q - 1] = tv;
                        int ti = ci[q]; ci[q] = ci[q - 1]; ci[q - 1] = ti;
                    }
            }
        }
    }
    #pragma unroll
    for (int q = 0; q < NCAND; ++q) {
        g_cI[((size_t)dir * NCAND + q) * N_DESC + i] = ci[q];
        g_cV[((size_t)dir * NCAND + q) * N_DESC + i] = cv[q];
    }
}

// ---- kernel 6: gap-gated fp32 rescore (one warp per row/col) --------------
__global__ void rescore_kernel() {
    const int lane = threadIdx.x & 31;
    const int w = threadIdx.x >> 5;
    const int row = blockIdx.x * 8 + w;
    const int dir = blockIdx.y;
    if (row >= N_DESC) return;

    int idx[NCAND]; float cv[NCAND];
    #pragma unroll
    for (int q = 0; q < NCAND; ++q) {
        idx[q] = g_cI[((size_t)dir * NCAND + q) * N_DESC + row];
        cv[q]  = g_cV[((size_t)dir * NCAND + q) * N_DESC + row];
    }

    // Fast path: screened gap decisive (>= ~14 sigma of bf16 noise) ->
    // screened argmax equals fp32 argmax; screened values accurate to ~7e-5.
    if (cv[0] - cv[1] > GAP_T) {
        if (lane == 0) {
            if (dir == 0) { g_aV1[row] = cv[0]; g_aV2[row] = cv[1]; g_aI1[row] = idx[0]; }
            else          { g_bV1[row] = cv[0]; g_bV2[row] = cv[1]; g_bI1[row] = idx[0]; }
        }
        return;
    }

    const float* X = dir ? g_fB : g_fA;
    const float* Y = dir ? g_fA : g_fB;
    float s[NCAND];
    #pragma unroll
    for (int q = 0; q < NCAND; ++q) s[q] = 0.f;
    const float4* xr = reinterpret_cast<const float4*>(X + (size_t)row * CH) + lane * 4;
    #pragma unroll
    for (int u = 0; u < 4; ++u) {
        float4 xa = xr[u];
        #pragma unroll
        for (int q = 0; q < NCAND; ++q) {
            float4 yb = *(reinterpret_cast<const float4*>(Y + (size_t)idx[q] * CH) +
                          lane * 4 + u);
            s[q] += xa.x * yb.x + xa.y * yb.y + xa.z * yb.z + xa.w * yb.w;
        }
    }
    #pragma unroll
    for (int m = 16; m > 0; m >>= 1)
        #pragma unroll
        for (int q = 0; q < NCAND; ++q)
            s[q] += __shfl_xor_sync(0xffffffffu, s[q], m);
    if (lane == 0) {
        float v1 = NEG_INF, v2 = NEG_INF; int i1 = 0;
        #pragma unroll
        for (int q = 0; q < NCAND; ++q) {
            if (s[q] > v1 || (s[q] == v1 && idx[q] < i1)) {
                v2 = v1; v1 = s[q]; i1 = idx[q];
            } else if (s[q] > v2) v2 = s[q];
        }
        if (dir == 0) { g_aV1[row] = v1; g_aV2[row] = v2; g_aI1[row] = i1; }
        else          { g_bV1[row] = v1; g_bV2[row] = v2; g_bI1[row] = i1; }
    }
}

// ---- kernel 7: mutual check + ratio test + output -------------------------
__global__ void match_kernel(float* __restrict__ out) {
    int i = blockIdx.x * blockDim.x + threadIdx.x;
    if (i >= N_DESC) return;
    float s1 = g_aV1[i], s2 = g_aV2[i];
    int   n12 = g_aI1[i];
    float r12 = (2.0f - 2.0f * s1) / (2.0f - 2.0f * s2 + EPS_T);
    int   n21 = g_bI1[n12];
    float r21 = (2.0f - 2.0f * g_bV1[n12]) / (2.0f - 2.0f * g_bV2[n12] + EPS_T);
    bool mask = (n21 == i) && (r12 <= RATIO_T) && (r21 <= RATIO_T);
    out[i]              = mask ? s1 : 0.0f;
    out[N_DESC + i]     = (float)n12;
    out[2 * N_DESC + i] = mask ? 1.0f : 0.0f;
}

// ---------------------------------------------------------------------------
extern "C" void kernel_launch(void* const* d_in, const int* in_sizes, int n_in,
                              void* d_out, int out_size) {
    const float* mA = (const float*)d_in[0];
    const float* mB = (const float*)d_in[1];
    float* out = (float*)d_out;

    cudaFuncSetAttribute(gemm_top2_kernel,
                         cudaFuncAttributeMaxDynamicSharedMemorySize, SMEM_GEMM);

    dim3 nb(N_DESC / 256, 2);
    norms_kernel<<<nb, 256>>>(mA, mB);

    dim3 pp(N_DESC / 64, CH / 64, 2);
    prep_kernel<<<pp, 256>>>(mA, mB);

    dim3 gb(NT, NT);
    gemm_top2_kernel<<<gb, 256, SMEM_GEMM>>>();

    dim3 r1(N_DESC / 256, 8, 2);
    reduce1_kernel<<<r1, 256>>>();

    dim3 cd(N_DESC / 256, 2);
    cand_kernel<<<cd, 256>>>();

    dim3 rs(N_DESC / 8, 2);
    rescore_kernel<<<rs, 256>>>();

    match_kernel<<<N_DESC / 256, 256>>>(out);
}